// round 11
// baseline (speedup 1.0000x reference)
#include <cuda_runtime.h>
#include <cstdint>

#define SQ   256
#define NH   16
#define HD   64
#define HIDW 1024
#define LOG2E 1.4426950408889634f

static __device__ float  g_Q[NH*SQ*HD];
static __device__ float  g_K[NH*SQ*HD + 256];      // padded: prefetch overshoot
static __device__ float  g_V[NH*SQ*HD];
static __device__ float  g_S[NH*SQ*SQ];
static __device__ float  g_P[NH*SQ*SQ];
static __device__ float2 g_AP[NH*SQ*SQ + 8];       // padded: prefetch overshoot
static __device__ float  g_P2[NH*SQ];
static __device__ float  g_Ctx[SQ*HIDW];
static __device__ float  g_Part[NH*SQ*HD];         // [row][d]

__device__ __forceinline__ float ex2f(float x){ float y; asm("ex2.approx.ftz.f32 %0, %1;" : "=f"(y) : "f"(x)); return y; }
__device__ __forceinline__ float rcpf(float x){ float y; asm("rcp.approx.ftz.f32 %0, %1;" : "=f"(y) : "f"(x)); return y; }
__device__ __forceinline__ uint32_t f2tf32(float x){ uint32_t r; asm("cvt.rna.tf32.f32 %0, %1;" : "=r"(r) : "f"(x)); return r; }
__device__ __forceinline__ void pfL1(const void* p){ asm volatile("prefetch.global.L1 [%0];" :: "l"(p)); }

__device__ __forceinline__ void mma8(float* c, const uint32_t* a, const uint32_t* b){
    asm volatile("mma.sync.aligned.m16n8k8.row.col.f32.tf32.tf32.f32 "
        "{%0,%1,%2,%3}, {%4,%5,%6,%7}, {%8,%9}, {%0,%1,%2,%3};"
        : "+f"(c[0]), "+f"(c[1]), "+f"(c[2]), "+f"(c[3])
        : "r"(a[0]), "r"(a[1]), "r"(a[2]), "r"(a[3]), "r"(b[0]), "r"(b[1]));
}

// ---------------------------------------------------------------------------
// tf32-split GEMM, double-buffered smem mainloop (3-term split = fp32-grade).
// MODE 0: fused = hidden @ Wqkv (+bias) -> scatter Q/K/V
// MODE 1: S[h]  = Q[h] @ K[h]^T   (B transposed at staging)
// MODE 2: Ctx   = P[h] @ V[h]
// MODE 3: out   = Ctx @ Wd (+bias+residual)
// ---------------------------------------------------------------------------
#define BSZ (32*72)

template<int MODE, int MT>
__global__ void __launch_bounds__(256, 1) mma_gemm_k(const float* __restrict__ Aext,
                                                     const float* __restrict__ Bext,
                                                     const float* __restrict__ bias,
                                                     const float* __restrict__ resid,
                                                     float* __restrict__ outp)
{
    constexpr int KT  = (MODE==1) ? 64 : (MODE==2) ? 256 : 1024;
    constexpr int NK  = KT/32;
    constexpr int LDA = (MODE==1) ? 64 : (MODE==2) ? 256 : 1024;
    constexpr int LDB = (MODE==0) ? 3072 : (MODE==1) ? 64 : (MODE==2) ? 64 : 1024;
    constexpr int BM  = 64*MT;
    constexpr int AST = BM + 8;
    constexpr int ASZ = 32*AST;
    constexpr int SETSZ = 2*ASZ + 2*BSZ;

    extern __shared__ float sm[];

    const int tid = threadIdx.x, lane = tid & 31, wid = tid >> 5;
    const int wm = wid >> 1, wn = wid & 1;
    const int tig = lane & 3, gid = lane >> 2;
    const int n0 = blockIdx.x*64, m0 = blockIdx.y*BM, z = blockIdx.z;

    const float* Ag; const float* Bg;
    if constexpr (MODE==0)      { Ag = Aext;                  Bg = Bext; }
    else if constexpr (MODE==1) { Ag = g_Q + z*SQ*HD;         Bg = g_K + z*SQ*HD; }
    else if constexpr (MODE==2) { Ag = g_P + (size_t)z*SQ*SQ; Bg = g_V + z*SQ*HD; }
    else                        { Ag = g_Ctx;                 Bg = Bext; }

    const int kqw = tid & 3, mrw = (tid >> 2) & 7, aw = tid >> 5;
    float4 pa[2*MT]; float4 pb[2]; float pbt[8];

    auto loadA = [&](int kt){
#pragma unroll
        for (int mi = 0; mi < MT; mi++)
#pragma unroll
            for (int ki = 0; ki < 2; ki++) {
                int m = aw*8 + mrw + 64*mi, kq = kqw + 4*ki;
                pa[mi*2+ki] = *(const float4*)(Ag + (size_t)(m0+m)*LDA + kt*32 + kq*4);
            }
    };
    auto loadB = [&](int kt){
        if constexpr (MODE==1) {
            int d = tid & 31, jb = (tid >> 5) * 8;
#pragma unroll
            for (int r = 0; r < 8; r++)
                pbt[r] = Bg[(size_t)(n0 + jb + r)*LDB + kt*32 + d];
        } else {
#pragma unroll
            for (int r = 0; r < 2; r++) {
                int idx = tid + 256*r, kr = idx >> 4, nq = idx & 15;
                pb[r] = *(const float4*)(Bg + (size_t)(kt*32 + kr)*LDB + n0 + nq*4);
            }
        }
    };
    auto stage = [&](int buf){
        float* Ah = sm + buf*SETSZ;
        float* Al = Ah + ASZ;
        float* Bh = Ah + 2*ASZ;
        float* Bl = Ah + 2*ASZ + BSZ;
#pragma unroll
        for (int mi = 0; mi < MT; mi++)
#pragma unroll
            for (int ki = 0; ki < 2; ki++) {
                int m = aw*8 + mrw + 64*mi, kq = kqw + 4*ki;
                int mb = m ^ ((kq & 3) << 3);
                float4 v = pa[mi*2+ki];
                float vv[4] = {v.x, v.y, v.z, v.w};
#pragma unroll
                for (int e = 0; e < 4; e++) {
                    uint32_t hb = f2tf32(vv[e]);
                    float hf = __uint_as_float(hb);
                    uint32_t lb = f2tf32(vv[e] - hf);
                    Ah[(kq*4+e)*AST + mb] = hf;
                    Al[(kq*4+e)*AST + mb] = __uint_as_float(lb);
                }
            }
        if constexpr (MODE==1) {
            int d = tid & 31, jb = (tid >> 5) * 8;
            int C = ((d >> 2) & 3) << 3;
#pragma unroll
            for (int r = 0; r < 8; r++) {
                uint32_t hb = f2tf32(pbt[r]);
                float hf = __uint_as_float(hb);
                uint32_t lb = f2tf32(pbt[r] - hf);
                int off = d*72 + ((jb + r) ^ C);
                Bh[off] = hf; Bl[off] = __uint_as_float(lb);
            }
        } else {
#pragma unroll
            for (int r = 0; r < 2; r++) {
                int idx = tid + 256*r, kr = idx >> 4, nq = idx & 15;
                int off = kr*72 + ((nq*4) ^ (((kr >> 2) & 3) << 3));
                float4 v = pb[r];
                float4 h4, l4;
                uint32_t b;
                b = f2tf32(v.x); h4.x = __uint_as_float(b); l4.x = __uint_as_float(f2tf32(v.x - h4.x));
                b = f2tf32(v.y); h4.y = __uint_as_float(b); l4.y = __uint_as_float(f2tf32(v.y - h4.y));
                b = f2tf32(v.z); h4.z = __uint_as_float(b); l4.z = __uint_as_float(f2tf32(v.z - h4.z));
                b = f2tf32(v.w); h4.w = __uint_as_float(b); l4.w = __uint_as_float(f2tf32(v.w - h4.w));
                *(float4*)(Bh + off) = h4;
                *(float4*)(Bl + off) = l4;
            }
        }
    };

    float acc[MT][4][4];
#pragma unroll
    for (int a = 0; a < MT; a++)
#pragma unroll
        for (int b = 0; b < 4; b++)
#pragma unroll
            for (int c = 0; c < 4; c++) acc[a][b][c] = 0.f;

    auto mmaOn = [&](int buf){
        const uint32_t* Ahu = (const uint32_t*)(sm + buf*SETSZ);
        const uint32_t* Alu = Ahu + ASZ;
        const uint32_t* Bhu = Ahu + 2*ASZ;
        const uint32_t* Blu = Ahu + 2*ASZ + BSZ;
#pragma unroll
        for (int ks = 0; ks < 4; ks++) {
            uint32_t ah[MT][4], al2[MT][4], bh[4][2], bl2[4][2];
            const int kA = ks*8 + tig;
            const int C0 = ((kA >> 2) & 3) << 3;
            const int C1 = (((kA + 4) >> 2) & 3) << 3;
#pragma unroll
            for (int mt = 0; mt < MT; mt++) {
                int m = wm*(16*MT) + mt*16 + gid;
                int mxa = m ^ C0, mya = m ^ C1;
                int i0 = kA*AST, i1 = (kA+4)*AST;
                ah[mt][0]  = Ahu[i0 + mxa];       ah[mt][1]  = Ahu[i0 + (mxa ^ 8)];
                ah[mt][2]  = Ahu[i1 + mya];       ah[mt][3]  = Ahu[i1 + (mya ^ 8)];
                al2[mt][0] = Alu[i0 + mxa];       al2[mt][1] = Alu[i0 + (mxa ^ 8)];
                al2[mt][2] = Alu[i1 + mya];       al2[mt][3] = Alu[i1 + (mya ^ 8)];
            }
#pragma unroll
            for (int nt = 0; nt < 4; nt++) {
                int n = wn*32 + nt*8 + gid;
                bh[nt][0]  = Bhu[kA*72 + (n ^ C0)];
                bh[nt][1]  = Bhu[(kA+4)*72 + (n ^ C1)];
                bl2[nt][0] = Blu[kA*72 + (n ^ C0)];
                bl2[nt][1] = Blu[(kA+4)*72 + (n ^ C1)];
            }
#pragma unroll
            for (int mt = 0; mt < MT; mt++)
#pragma unroll
                for (int nt = 0; nt < 4; nt++) {
                    mma8(acc[mt][nt], ah[mt],  bh[nt]);
                    mma8(acc[mt][nt], ah[mt],  bl2[nt]);
                    mma8(acc[mt][nt], al2[mt], bh[nt]);
                }
        }
    };

    loadA(0); loadB(0);
    stage(0);
    __syncthreads();
    for (int kt = 0; kt < NK; kt++) {
        if (kt + 1 < NK) { loadA(kt+1); loadB(kt+1); }
        mmaOn(kt & 1);
        if (kt + 1 < NK) stage((kt+1) & 1);
        __syncthreads();
    }

#pragma unroll
    for (int mt = 0; mt < MT; mt++) {
        int m = m0 + wm*(16*MT) + mt*16 + gid;
#pragma unroll
        for (int nt = 0; nt < 4; nt++) {
            int n = n0 + wn*32 + nt*8 + tig*2;
            float c0 = acc[mt][nt][0], c1 = acc[mt][nt][1];
            float c2 = acc[mt][nt][2], c3 = acc[mt][nt][3];
            if constexpr (MODE==0) {
                float2 bb = *(const float2*)(bias + n);
                int hh = n / 192, rem = n - hh*192, wch = rem >> 6, d = rem & 63;
                float* base = (wch == 0) ? g_Q : (wch == 1) ? g_K : g_V;
                *(float2*)(base + (size_t)(hh*SQ + m)*HD + d)     = make_float2(c0 + bb.x, c1 + bb.y);
                *(float2*)(base + (size_t)(hh*SQ + m + 8)*HD + d) = make_float2(c2 + bb.x, c3 + bb.y);
            } else if constexpr (MODE==1) {
                *(float2*)(g_S + (size_t)(z*SQ + m)*SQ + n)     = make_float2(c0, c1);
                *(float2*)(g_S + (size_t)(z*SQ + m + 8)*SQ + n) = make_float2(c2, c3);
            } else if constexpr (MODE==2) {
                *(float2*)(g_Ctx + (size_t)m*HIDW + z*HD + n)       = make_float2(c0, c1);
                *(float2*)(g_Ctx + (size_t)(m + 8)*HIDW + z*HD + n) = make_float2(c2, c3);
            } else {
                float2 bb = *(const float2*)(bias + n);
                float2 r0 = *(const float2*)(resid + (size_t)m*HIDW + n);
                float2 r1 = *(const float2*)(resid + (size_t)(m + 8)*HIDW + n);
                *(float2*)(outp + (size_t)m*HIDW + n)       = make_float2(c0 + bb.x + r0.x, c1 + bb.y + r0.y);
                *(float2*)(outp + (size_t)(m + 8)*HIDW + n) = make_float2(c2 + bb.x + r1.x, c3 + bb.y + r1.y);
            }
        }
    }
}

// ---------------------------------------------------------------------------
// Warp-per-row softmax: 8 warps/block, lane owns 8 j's, shfl-only reductions.
// ---------------------------------------------------------------------------
__global__ void __launch_bounds__(256) softmax_k(const float* __restrict__ alibi,
                                                 const float* __restrict__ mask)
{
    const int w = threadIdx.x >> 5, ln = threadIdx.x & 31;
    const int row = blockIdx.x*8 + w;
    const int h = row >> 8, i = row & 255;
    const int j0 = ln*8;

    float4 s0 = *(const float4*)(g_S + (size_t)row*SQ + j0);
    float4 s1 = *(const float4*)(g_S + (size_t)row*SQ + j0 + 4);
    float4 a0 = *(const float4*)(alibi + h*SQ + j0);
    float4 a1 = *(const float4*)(alibi + h*SQ + j0 + 4);
    float4 k0 = *(const float4*)(mask + (size_t)i*SQ + j0);
    float4 k1 = *(const float4*)(mask + (size_t)i*SQ + j0 + 4);

    float sv[8] = {s0.x, s0.y, s0.z, s0.w, s1.x, s1.y, s1.z, s1.w};
    float al[8] = {a0.x, a0.y, a0.z, a0.w, a1.x, a1.y, a1.z, a1.w};
    float mk[8] = {k0.x, k0.y, k0.z, k0.w, k1.x, k1.y, k1.z, k1.w};

    float sc[8];
#pragma unroll
    for (int t = 0; t < 8; t++) sc[t] = fmaf(0.125f, sv[t], al[t]) + mk[t];

    float mx = sc[0];
#pragma unroll
    for (int t = 1; t < 8; t++) mx = fmaxf(mx, sc[t]);
#pragma unroll
    for (int o = 16; o; o >>= 1) mx = fmaxf(mx, __shfl_xor_sync(0xffffffffu, mx, o));

    float e[8], tot = 0.f;
#pragma unroll
    for (int t = 0; t < 8; t++) { e[t] = ex2f((sc[t] - mx) * LOG2E); tot += e[t]; }
#pragma unroll
    for (int o = 16; o; o >>= 1) tot += __shfl_xor_sync(0xffffffffu, tot, o);

    float iz = rcpf(tot);
    float p[8];
#pragma unroll
    for (int t = 0; t < 8; t++) p[t] = e[t] * iz;

    *(float4*)(g_P + (size_t)row*SQ + j0)     = make_float4(p[0], p[1], p[2], p[3]);
    *(float4*)(g_P + (size_t)row*SQ + j0 + 4) = make_float4(p[4], p[5], p[6], p[7]);

    float av[8];
#pragma unroll
    for (int t = 0; t < 8; t++) av[t] = (j0 + t <= i) ? ex2f(sv[t] * (LOG2E/64.f)) : 0.f;

    float4* app = (float4*)(g_AP + (size_t)row*SQ);
    app[ln*4 + 0] = make_float4(av[0], p[0], av[1], p[1]);
    app[ln*4 + 1] = make_float4(av[2], p[2], av[3], p[3]);
    app[ln*4 + 2] = make_float4(av[4], p[4], av[5], p[5]);
    app[ln*4 + 3] = make_float4(av[6], p[6], av[7], p[7]);

    float pq = 0.f;
#pragma unroll
    for (int t = 0; t < 8; t++) pq = fmaf(p[t], p[t], pq);
#pragma unroll
    for (int o = 16; o; o >>= 1) pq += __shfl_xor_sync(0xffffffffu, pq, o);
    if (ln == 0) g_P2[row] = pq;
}

// ---------------------------------------------------------------------------
// qk_importance v4: one block per (h, pair(i1, 255-i1)); 256 threads =
// 32 d-pairs (float2 K) x 8 j-splits.  Software-pipelined: next iteration's
// K/AP preloaded into registers before computing the current one, plus L1
// prefetch at distance +32.  Bounds rounded up to x16 (A_j==0 for masked j
// => overshoot contributes 0).  Deterministic smem combine over the splits.
// ---------------------------------------------------------------------------
__global__ void __launch_bounds__(256) importance_k()
{
    __shared__ float sm[6*512];
    const int tid = threadIdx.x;
    const int dp  = tid & 31;                 // d-pair: d = 2dp, 2dp+1
    const int par = tid >> 5;                 // j-split 0..7
    const int h   = blockIdx.x >> 7;
    const int i1  = blockIdx.x & 127;
    const int i2  = 255 - i1;
    const int row1 = h*SQ + i1, row2 = h*SQ + i2;

    const float cc = -LOG2E/64.f;
    float2 q1 = *(const float2*)(g_Q + row1*HD + 2*dp);
    float2 q2 = *(const float2*)(g_Q + row2*HD + 2*dp);
    const float qe1x = q1.x*cc, qe1y = q1.y*cc, qe2x = q2.x*cc, qe2y = q2.y*cc;
    const float2* kp  = (const float2*)(g_K + (size_t)h*SQ*HD) + dp;   // kp[j*32]
    const float4* ap1 = (const float4*)(g_AP + (size_t)row1*SQ);       // [j/2]
    const float4* ap2 = (const float4*)(g_AP + (size_t)row2*SQ);

    float Z1x=0.f, Z1y=0.f, W1x=0.f, W1y=0.f, P1x=0.f, P1y=0.f;
    float Z2x=0.f, Z2y=0.f, W2x=0.f, W2y=0.f, P2x=0.f, P2y=0.f;

    const int e1 = (i1 + 16) & ~15;           // roundup16(i1+1) <= 128
    const int e2 = (i2 + 16) & ~15;           // <= 256
    int j = 2*par;

    // pipeline prologue
    float2 k0 = kp[(size_t)j*32], k1 = kp[(size_t)(j+1)*32];
    float4 u  = ap1[j>>1];
    float4 v  = ap2[j>>1];

    for (; j < e1; j += 16) {                 // phase 1: both rows
        // depth-1 register prefetch (padded arrays make overshoot safe)
        float2 nk0 = kp[(size_t)(j+16)*32], nk1 = kp[(size_t)(j+17)*32];
        float4 nu  = ap1[(j+16)>>1];
        float4 nv  = ap2[(j+16)>>1];
        pfL1(&kp[(size_t)(j+32)*32]);
        pfL1(&ap2[(j+32)>>1]);

        float E0x = ex2f(qe1x*k0.x), E0y = ex2f(qe1y*k0.y);
        float E1x = ex2f(qe1x*k1.x), E1y = ex2f(qe1y*k1.y);
        float F0x = ex2f(qe2x*k0.x), F0y = ex2f(qe2y*k0.y);
        float F1x = ex2f(qe2x*k1.x), F1y = ex2f(qe2y*k1.y);
        float w;
        w = u.x*E0x; Z1x += w; W1x = fmaf(w,w,W1x); P1x = fmaf(w,u.y,P1x);
        w = u.x*E0y; Z1y += w; W1y = fmaf(w,w,W1y); P1y = fmaf(w,u.y,P1y);
        w = u.z*E1x; Z1x += w; W1x = fmaf(w,w,W1x); P1x = fmaf(w,u.w,P1x);
        w = u.z*E1y; Z1y += w; W1y = fmaf(w,w,W1y); P1y = fmaf(w,u.w,P1y);
        w = v.x*F0x; Z2x += w; W2x = fmaf(w,w,W2x); P2x = fmaf(w,v.y,P2x);
        w = v.x*F0y; Z2y += w; W2y = fmaf(w,w,W2y); P2y = fmaf(w,v.y,P2y);
        w = v.z*F1x; Z2x += w; W2x = fmaf(w,w,W2x); P2x = fmaf(w,v.w,P2x);
        w = v.z*F1y; Z2y += w; W2y = fmaf(w,w,W2y); P2y = fmaf(w,v.w,P2y);

        k0 = nk0; k1 = nk1; u = nu; v = nv;
    }
    // phase transition: registers already hold entry for j == e1
    for (; j < e2; j += 16) {                 // phase 2: row2 only
        float2 nk0 = kp[(size_t)(j+16)*32], nk1 = kp[(size_t)(j+17)*32];
        float4 nv  = ap2[(j+16)>>1];
        pfL1(&kp[(size_t)(j+32)*32]);
        pfL1(&ap2[(j+32)>>1]);

        float F0x = ex2f(qe2x*k0.x), F0y = ex2f(qe2y*k0.y);
        float F1x = ex2f(qe2x*k1.x), F1y = ex2f(qe2y*k1.y);
        float w;
        w = v.x*F0x; Z2x += w; W2x = fmaf(w,w,W2x); P2x = fmaf(w,v.y,P2x);
        w = v.x*F0y; Z2y += w; W2y = fmaf(w,w,W2y); P2y = fmaf(w,v.y,P2y);
        w = v.z*F1x; Z2x += w; W2x = fmaf(w,w,W2x); P2x = fmaf(w,v.w,P2x);
        w = v.z*F1y; Z2y += w; W2y = fmaf(w,w,W2y); P2y = fmaf(w,v.w,P2y);

        k0 = nk0; k1 = nk1; v = nv;
    }

    // smem combine: layout [q(6)][par(8)][d(64)], float2 stores (bank-clean)
    float2* s2 = (float2*)sm;
    const int base = par*32 + dp;
    s2[0*256 + base] = make_float2(Z1x, Z1y);
    s2[1*256 + base] = make_float2(W1x, W1y);
    s2[2*256 + base] = make_float2(P1x, P1y);
    s2[3*256 + base] = make_float2(Z2x, Z2y);
    s2[4*256 + base] = make_float2(W2x, W2y);
    s2[5*256 + base] = make_float2(P2x, P2y);
    __syncthreads();
    if (tid < 128) {
        const int r = tid >> 6, d = tid & 63;
        const int qb = 3*r;
        float Z = 0.f, W = 0.f, P = 0.f;
#pragma unroll
        for (int pp = 0; pp < 8; pp++) {
            Z += sm[(qb+0)*512 + pp*64 + d];
            W += sm[(qb+1)*512 + pp*64 + d];
            P += sm[(qb+2)*512 + pp*64 + d];
        }
        const int row = r ? row2 : row1;
        float iz = rcpf(Z);
        g_Part[row*HD + d] = fmaf(W*iz, iz, -2.f*P*iz) + g_P2[row];
    }
}

// Single-kernel deterministic reduction: block per head.
__global__ void __launch_bounds__(256) reduce_imp(float* __restrict__ imp)
{
    __shared__ float s[4][64];
    const int h = blockIdx.x, rr = threadIdx.x >> 6, d = threadIdx.x & 63;
    float s0 = 0.f;
#pragma unroll 8
    for (int r = 0; r < 64; ++r)
        s0 += g_Part[(h*SQ + rr*64 + r)*HD + d];
    s[rr][d] = s0;
    __syncthreads();
    if (threadIdx.x < 64)
        imp[h*64 + threadIdx.x] = (s[0][threadIdx.x] + s[1][threadIdx.x])
                                + (s[2][threadIdx.x] + s[3][threadIdx.x]);
}

// ---------------------------------------------------------------------------
extern "C" void kernel_launch(void* const* d_in, const int* in_sizes, int n_in,
                              void* d_out, int out_size)
{
    (void)in_sizes; (void)n_in; (void)out_size;
    const float* hidden   = (const float*)d_in[0];
    const float* residual = (const float*)d_in[1];
    const float* alibi    = (const float*)d_in[2];
    const float* amask    = (const float*)d_in[3];
    const float* Wqkv     = (const float*)d_in[4];
    const float* bqkv     = (const float*)d_in[5];
    const float* Wd       = (const float*)d_in[6];
    const float* bd       = (const float*)d_in[7];
    float* out = (float*)d_out;

    constexpr int SMEM1 = 2*(2*32*72  + 2*BSZ)*4;   // MT=1 DB: 73728
    constexpr int SMEM2 = 2*(2*32*136 + 2*BSZ)*4;   // MT=2 DB: 106496

    cudaFuncSetAttribute(mma_gemm_k<0,1>, cudaFuncAttributeMaxDynamicSharedMemorySize, SMEM1);
    cudaFuncSetAttribute(mma_gemm_k<1,2>, cudaFuncAttributeMaxDynamicSharedMemorySize, SMEM2);
    cudaFuncSetAttribute(mma_gemm_k<2,1>, cudaFuncAttributeMaxDynamicSharedMemorySize, SMEM1);
    cudaFuncSetAttribute(mma_gemm_k<3,1>, cudaFuncAttributeMaxDynamicSharedMemorySize, SMEM1);

    // 1. QKV projection + Q/K/V scatter (192 blocks)
    mma_gemm_k<0,1><<<dim3(48,4,1), 256, SMEM1>>>(hidden, Wqkv, bqkv, nullptr, nullptr);
    // 2. scores S = Q K^T per head (128 blocks)
    mma_gemm_k<1,2><<<dim3(4,2,16), 256, SMEM2>>>(nullptr, nullptr, nullptr, nullptr, nullptr);
    // 3. warp-per-row softmax (p, A, P2)
    softmax_k<<<512, 256>>>(alibi, amask);
    // 4. qk importance (pipelined v4, 2048 pair-blocks)
    importance_k<<<2048, 256>>>();
    // 5. context = P V per head
    mma_gemm_k<2,1><<<dim3(1,4,16), 256, SMEM1>>>(nullptr, nullptr, nullptr, nullptr, nullptr);
    // 6. dense + bias + residual
    mma_gemm_k<3,1><<<dim3(16,4,1), 256, SMEM1>>>(nullptr, Wd, bd, residual, out);
    // 7. deterministic importance reduce
    reduce_imp<<<16, 256>>>(out + SQ*HIDW);
}

// round 12
// speedup vs baseline: 1.0463x; 1.0463x over previous
#include <cuda_runtime.h>
#include <cstdint>

#define SQ   256
#define NH   16
#define HD   64
#define HIDW 1024
#define LOG2E 1.4426950408889634f

static __device__ float  g_Q[NH*SQ*HD];
static __device__ float  g_K[NH*SQ*HD + 256];      // padded: prefetch overshoot
static __device__ float  g_V[NH*SQ*HD];
static __device__ float  g_S[NH*SQ*SQ];
static __device__ float  g_P[NH*SQ*SQ];
static __device__ float2 g_AP[NH*SQ*SQ + 8];       // padded: prefetch overshoot
static __device__ float  g_P2[NH*SQ];
static __device__ float  g_Ctx[SQ*HIDW];
static __device__ float  g_Part[NH*SQ*HD];         // [row][d]

__device__ __forceinline__ float ex2f(float x){ float y; asm("ex2.approx.ftz.f32 %0, %1;" : "=f"(y) : "f"(x)); return y; }
__device__ __forceinline__ float rcpf(float x){ float y; asm("rcp.approx.ftz.f32 %0, %1;" : "=f"(y) : "f"(x)); return y; }
__device__ __forceinline__ uint32_t f2tf32(float x){ uint32_t r; asm("cvt.rna.tf32.f32 %0, %1;" : "=r"(r) : "f"(x)); return r; }
__device__ __forceinline__ void pfL1(const void* p){ asm volatile("prefetch.global.L1 [%0];" :: "l"(p)); }

__device__ __forceinline__ void mma8(float* c, const uint32_t* a, const uint32_t* b){
    asm volatile("mma.sync.aligned.m16n8k8.row.col.f32.tf32.tf32.f32 "
        "{%0,%1,%2,%3}, {%4,%5,%6,%7}, {%8,%9}, {%0,%1,%2,%3};"
        : "+f"(c[0]), "+f"(c[1]), "+f"(c[2]), "+f"(c[3])
        : "r"(a[0]), "r"(a[1]), "r"(a[2]), "r"(a[3]), "r"(b[0]), "r"(b[1]));
}

// ---------------------------------------------------------------------------
// tf32-split GEMM, double-buffered smem mainloop (3-term split = fp32-grade).
// MODE 0: fused = hidden @ Wqkv (+bias) -> scatter Q/K/V
// MODE 1: S[h]  = Q[h] @ K[h]^T   (B transposed at staging)
// MODE 2: Ctx   = P[h] @ V[h]
// MODE 3: out   = Ctx @ Wd (+bias+residual)
// ---------------------------------------------------------------------------
#define BSZ (32*72)

template<int MODE, int MT>
__global__ void __launch_bounds__(256, 1) mma_gemm_k(const float* __restrict__ Aext,
                                                     const float* __restrict__ Bext,
                                                     const float* __restrict__ bias,
                                                     const float* __restrict__ resid,
                                                     float* __restrict__ outp)
{
    constexpr int KT  = (MODE==1) ? 64 : (MODE==2) ? 256 : 1024;
    constexpr int NK  = KT/32;
    constexpr int LDA = (MODE==1) ? 64 : (MODE==2) ? 256 : 1024;
    constexpr int LDB = (MODE==0) ? 3072 : (MODE==1) ? 64 : (MODE==2) ? 64 : 1024;
    constexpr int BM  = 64*MT;
    constexpr int AST = BM + 8;
    constexpr int ASZ = 32*AST;
    constexpr int SETSZ = 2*ASZ + 2*BSZ;

    extern __shared__ float sm[];

    const int tid = threadIdx.x, lane = tid & 31, wid = tid >> 5;
    const int wm = wid >> 1, wn = wid & 1;
    const int tig = lane & 3, gid = lane >> 2;
    const int n0 = blockIdx.x*64, m0 = blockIdx.y*BM, z = blockIdx.z;

    const float* Ag; const float* Bg;
    if constexpr (MODE==0)      { Ag = Aext;                  Bg = Bext; }
    else if constexpr (MODE==1) { Ag = g_Q + z*SQ*HD;         Bg = g_K + z*SQ*HD; }
    else if constexpr (MODE==2) { Ag = g_P + (size_t)z*SQ*SQ; Bg = g_V + z*SQ*HD; }
    else                        { Ag = g_Ctx;                 Bg = Bext; }

    const int kqw = tid & 3, mrw = (tid >> 2) & 7, aw = tid >> 5;
    float4 pa[2*MT]; float4 pb[2]; float pbt[8];

    auto loadA = [&](int kt){
#pragma unroll
        for (int mi = 0; mi < MT; mi++)
#pragma unroll
            for (int ki = 0; ki < 2; ki++) {
                int m = aw*8 + mrw + 64*mi, kq = kqw + 4*ki;
                pa[mi*2+ki] = *(const float4*)(Ag + (size_t)(m0+m)*LDA + kt*32 + kq*4);
            }
    };
    auto loadB = [&](int kt){
        if constexpr (MODE==1) {
            int d = tid & 31, jb = (tid >> 5) * 8;
#pragma unroll
            for (int r = 0; r < 8; r++)
                pbt[r] = Bg[(size_t)(n0 + jb + r)*LDB + kt*32 + d];
        } else {
#pragma unroll
            for (int r = 0; r < 2; r++) {
                int idx = tid + 256*r, kr = idx >> 4, nq = idx & 15;
                pb[r] = *(const float4*)(Bg + (size_t)(kt*32 + kr)*LDB + n0 + nq*4);
            }
        }
    };
    auto stage = [&](int buf){
        float* Ah = sm + buf*SETSZ;
        float* Al = Ah + ASZ;
        float* Bh = Ah + 2*ASZ;
        float* Bl = Ah + 2*ASZ + BSZ;
#pragma unroll
        for (int mi = 0; mi < MT; mi++)
#pragma unroll
            for (int ki = 0; ki < 2; ki++) {
                int m = aw*8 + mrw + 64*mi, kq = kqw + 4*ki;
                int mb = m ^ ((kq & 3) << 3);
                float4 v = pa[mi*2+ki];
                float vv[4] = {v.x, v.y, v.z, v.w};
#pragma unroll
                for (int e = 0; e < 4; e++) {
                    uint32_t hb = f2tf32(vv[e]);
                    float hf = __uint_as_float(hb);
                    uint32_t lb = f2tf32(vv[e] - hf);
                    Ah[(kq*4+e)*AST + mb] = hf;
                    Al[(kq*4+e)*AST + mb] = __uint_as_float(lb);
                }
            }
        if constexpr (MODE==1) {
            int d = tid & 31, jb = (tid >> 5) * 8;
            int C = ((d >> 2) & 3) << 3;
#pragma unroll
            for (int r = 0; r < 8; r++) {
                uint32_t hb = f2tf32(pbt[r]);
                float hf = __uint_as_float(hb);
                uint32_t lb = f2tf32(pbt[r] - hf);
                int off = d*72 + ((jb + r) ^ C);
                Bh[off] = hf; Bl[off] = __uint_as_float(lb);
            }
        } else {
#pragma unroll
            for (int r = 0; r < 2; r++) {
                int idx = tid + 256*r, kr = idx >> 4, nq = idx & 15;
                int off = kr*72 + ((nq*4) ^ (((kr >> 2) & 3) << 3));
                float4 v = pb[r];
                float4 h4, l4;
                uint32_t b;
                b = f2tf32(v.x); h4.x = __uint_as_float(b); l4.x = __uint_as_float(f2tf32(v.x - h4.x));
                b = f2tf32(v.y); h4.y = __uint_as_float(b); l4.y = __uint_as_float(f2tf32(v.y - h4.y));
                b = f2tf32(v.z); h4.z = __uint_as_float(b); l4.z = __uint_as_float(f2tf32(v.z - h4.z));
                b = f2tf32(v.w); h4.w = __uint_as_float(b); l4.w = __uint_as_float(f2tf32(v.w - h4.w));
                *(float4*)(Bh + off) = h4;
                *(float4*)(Bl + off) = l4;
            }
        }
    };

    float acc[MT][4][4];
#pragma unroll
    for (int a = 0; a < MT; a++)
#pragma unroll
        for (int b = 0; b < 4; b++)
#pragma unroll
            for (int c = 0; c < 4; c++) acc[a][b][c] = 0.f;

    auto mmaOn = [&](int buf){
        const uint32_t* Ahu = (const uint32_t*)(sm + buf*SETSZ);
        const uint32_t* Alu = Ahu + ASZ;
        const uint32_t* Bhu = Ahu + 2*ASZ;
        const uint32_t* Blu = Ahu + 2*ASZ + BSZ;
#pragma unroll
        for (int ks = 0; ks < 4; ks++) {
            uint32_t ah[MT][4], al2[MT][4], bh[4][2], bl2[4][2];
            const int kA = ks*8 + tig;
            const int C0 = ((kA >> 2) & 3) << 3;
            const int C1 = (((kA + 4) >> 2) & 3) << 3;
#pragma unroll
            for (int mt = 0; mt < MT; mt++) {
                int m = wm*(16*MT) + mt*16 + gid;
                int mxa = m ^ C0, mya = m ^ C1;
                int i0 = kA*AST, i1 = (kA+4)*AST;
                ah[mt][0]  = Ahu[i0 + mxa];       ah[mt][1]  = Ahu[i0 + (mxa ^ 8)];
                ah[mt][2]  = Ahu[i1 + mya];       ah[mt][3]  = Ahu[i1 + (mya ^ 8)];
                al2[mt][0] = Alu[i0 + mxa];       al2[mt][1] = Alu[i0 + (mxa ^ 8)];
                al2[mt][2] = Alu[i1 + mya];       al2[mt][3] = Alu[i1 + (mya ^ 8)];
            }
#pragma unroll
            for (int nt = 0; nt < 4; nt++) {
                int n = wn*32 + nt*8 + gid;
                bh[nt][0]  = Bhu[kA*72 + (n ^ C0)];
                bh[nt][1]  = Bhu[(kA+4)*72 + (n ^ C1)];
                bl2[nt][0] = Blu[kA*72 + (n ^ C0)];
                bl2[nt][1] = Blu[(kA+4)*72 + (n ^ C1)];
            }
#pragma unroll
            for (int mt = 0; mt < MT; mt++)
#pragma unroll
                for (int nt = 0; nt < 4; nt++) {
                    mma8(acc[mt][nt], ah[mt],  bh[nt]);
                    mma8(acc[mt][nt], ah[mt],  bl2[nt]);
                    mma8(acc[mt][nt], al2[mt], bh[nt]);
                }
        }
    };

    loadA(0); loadB(0);
    stage(0);
    __syncthreads();
    for (int kt = 0; kt < NK; kt++) {
        if (kt + 1 < NK) { loadA(kt+1); loadB(kt+1); }
        mmaOn(kt & 1);
        if (kt + 1 < NK) stage((kt+1) & 1);
        __syncthreads();
    }

#pragma unroll
    for (int mt = 0; mt < MT; mt++) {
        int m = m0 + wm*(16*MT) + mt*16 + gid;
#pragma unroll
        for (int nt = 0; nt < 4; nt++) {
            int n = n0 + wn*32 + nt*8 + tig*2;
            float c0 = acc[mt][nt][0], c1 = acc[mt][nt][1];
            float c2 = acc[mt][nt][2], c3 = acc[mt][nt][3];
            if constexpr (MODE==0) {
                float2 bb = *(const float2*)(bias + n);
                int hh = n / 192, rem = n - hh*192, wch = rem >> 6, d = rem & 63;
                float* base = (wch == 0) ? g_Q : (wch == 1) ? g_K : g_V;
                *(float2*)(base + (size_t)(hh*SQ + m)*HD + d)     = make_float2(c0 + bb.x, c1 + bb.y);
                *(float2*)(base + (size_t)(hh*SQ + m + 8)*HD + d) = make_float2(c2 + bb.x, c3 + bb.y);
            } else if constexpr (MODE==1) {
                *(float2*)(g_S + (size_t)(z*SQ + m)*SQ + n)     = make_float2(c0, c1);
                *(float2*)(g_S + (size_t)(z*SQ + m + 8)*SQ + n) = make_float2(c2, c3);
            } else if constexpr (MODE==2) {
                *(float2*)(g_Ctx + (size_t)m*HIDW + z*HD + n)       = make_float2(c0, c1);
                *(float2*)(g_Ctx + (size_t)(m + 8)*HIDW + z*HD + n) = make_float2(c2, c3);
            } else {
                float2 bb = *(const float2*)(bias + n);
                float2 r0 = *(const float2*)(resid + (size_t)m*HIDW + n);
                float2 r1 = *(const float2*)(resid + (size_t)(m + 8)*HIDW + n);
                *(float2*)(outp + (size_t)m*HIDW + n)       = make_float2(c0 + bb.x + r0.x, c1 + bb.y + r0.y);
                *(float2*)(outp + (size_t)(m + 8)*HIDW + n) = make_float2(c2 + bb.x + r1.x, c3 + bb.y + r1.y);
            }
        }
    }
}

// ---------------------------------------------------------------------------
// Warp-per-row softmax: 8 warps/block, lane owns 8 j's, shfl-only reductions.
// ---------------------------------------------------------------------------
__global__ void __launch_bounds__(256) softmax_k(const float* __restrict__ alibi,
                                                 const float* __restrict__ mask)
{
    const int w = threadIdx.x >> 5, ln = threadIdx.x & 31;
    const int row = blockIdx.x*8 + w;
    const int h = row >> 8, i = row & 255;
    const int j0 = ln*8;

    float4 s0 = *(const float4*)(g_S + (size_t)row*SQ + j0);
    float4 s1 = *(const float4*)(g_S + (size_t)row*SQ + j0 + 4);
    float4 a0 = *(const float4*)(alibi + h*SQ + j0);
    float4 a1 = *(const float4*)(alibi + h*SQ + j0 + 4);
    float4 k0 = *(const float4*)(mask + (size_t)i*SQ + j0);
    float4 k1 = *(const float4*)(mask + (size_t)i*SQ + j0 + 4);

    float sv[8] = {s0.x, s0.y, s0.z, s0.w, s1.x, s1.y, s1.z, s1.w};
    float al[8] = {a0.x, a0.y, a0.z, a0.w, a1.x, a1.y, a1.z, a1.w};
    float mk[8] = {k0.x, k0.y, k0.z, k0.w, k1.x, k1.y, k1.z, k1.w};

    float sc[8];
#pragma unroll
    for (int t = 0; t < 8; t++) sc[t] = fmaf(0.125f, sv[t], al[t]) + mk[t];

    float mx = sc[0];
#pragma unroll
    for (int t = 1; t < 8; t++) mx = fmaxf(mx, sc[t]);
#pragma unroll
    for (int o = 16; o; o >>= 1) mx = fmaxf(mx, __shfl_xor_sync(0xffffffffu, mx, o));

    float e[8], tot = 0.f;
#pragma unroll
    for (int t = 0; t < 8; t++) { e[t] = ex2f((sc[t] - mx) * LOG2E); tot += e[t]; }
#pragma unroll
    for (int o = 16; o; o >>= 1) tot += __shfl_xor_sync(0xffffffffu, tot, o);

    float iz = rcpf(tot);
    float p[8];
#pragma unroll
    for (int t = 0; t < 8; t++) p[t] = e[t] * iz;

    *(float4*)(g_P + (size_t)row*SQ + j0)     = make_float4(p[0], p[1], p[2], p[3]);
    *(float4*)(g_P + (size_t)row*SQ + j0 + 4) = make_float4(p[4], p[5], p[6], p[7]);

    float av[8];
#pragma unroll
    for (int t = 0; t < 8; t++) av[t] = (j0 + t <= i) ? ex2f(sv[t] * (LOG2E/64.f)) : 0.f;

    float4* app = (float4*)(g_AP + (size_t)row*SQ);
    app[ln*4 + 0] = make_float4(av[0], p[0], av[1], p[1]);
    app[ln*4 + 1] = make_float4(av[2], p[2], av[3], p[3]);
    app[ln*4 + 2] = make_float4(av[4], p[4], av[5], p[5]);
    app[ln*4 + 3] = make_float4(av[6], p[6], av[7], p[7]);

    float pq = 0.f;
#pragma unroll
    for (int t = 0; t < 8; t++) pq = fmaf(p[t], p[t], pq);
#pragma unroll
    for (int o = 16; o; o >>= 1) pq += __shfl_xor_sync(0xffffffffu, pq, o);
    if (ln == 0) g_P2[row] = pq;
}

// ---------------------------------------------------------------------------
// qk_importance v4: one block per (h, pair(i1, 255-i1)); 256 threads =
// 32 d-pairs (float2 K) x 8 j-splits.  Software-pipelined (depth-1 register
// prefetch + L1 prefetch at +32).  Bounds rounded to x16 (A_j==0 masked).
// Deterministic smem combine over the splits.
// ---------------------------------------------------------------------------
__global__ void __launch_bounds__(256) importance_k()
{
    __shared__ float sm[6*512];
    const int tid = threadIdx.x;
    const int dp  = tid & 31;
    const int par = tid >> 5;
    const int h   = blockIdx.x >> 7;
    const int i1  = blockIdx.x & 127;
    const int i2  = 255 - i1;
    const int row1 = h*SQ + i1, row2 = h*SQ + i2;

    const float cc = -LOG2E/64.f;
    float2 q1 = *(const float2*)(g_Q + row1*HD + 2*dp);
    float2 q2 = *(const float2*)(g_Q + row2*HD + 2*dp);
    const float qe1x = q1.x*cc, qe1y = q1.y*cc, qe2x = q2.x*cc, qe2y = q2.y*cc;
    const float2* kp  = (const float2*)(g_K + (size_t)h*SQ*HD) + dp;
    const float4* ap1 = (const float4*)(g_AP + (size_t)row1*SQ);
    const float4* ap2 = (const float4*)(g_AP + (size_t)row2*SQ);

    float Z1x=0.f, Z1y=0.f, W1x=0.f, W1y=0.f, P1x=0.f, P1y=0.f;
    float Z2x=0.f, Z2y=0.f, W2x=0.f, W2y=0.f, P2x=0.f, P2y=0.f;

    const int e1 = (i1 + 16) & ~15;
    const int e2 = (i2 + 16) & ~15;
    int j = 2*par;

    float2 k0 = kp[(size_t)j*32], k1 = kp[(size_t)(j+1)*32];
    float4 u  = ap1[j>>1];
    float4 v  = ap2[j>>1];

    for (; j < e1; j += 16) {
        float2 nk0 = kp[(size_t)(j+16)*32], nk1 = kp[(size_t)(j+17)*32];
        float4 nu  = ap1[(j+16)>>1];
        float4 nv  = ap2[(j+16)>>1];
        pfL1(&kp[(size_t)(j+32)*32]);
        pfL1(&ap2[(j+32)>>1]);

        float E0x = ex2f(qe1x*k0.x), E0y = ex2f(qe1y*k0.y);
        float E1x = ex2f(qe1x*k1.x), E1y = ex2f(qe1y*k1.y);
        float F0x = ex2f(qe2x*k0.x), F0y = ex2f(qe2y*k0.y);
        float F1x = ex2f(qe2x*k1.x), F1y = ex2f(qe2y*k1.y);
        float w;
        w = u.x*E0x; Z1x += w; W1x = fmaf(w,w,W1x); P1x = fmaf(w,u.y,P1x);
        w = u.x*E0y; Z1y += w; W1y = fmaf(w,w,W1y); P1y = fmaf(w,u.y,P1y);
        w = u.z*E1x; Z1x += w; W1x = fmaf(w,w,W1x); P1x = fmaf(w,u.w,P1x);
        w = u.z*E1y; Z1y += w; W1y = fmaf(w,w,W1y); P1y = fmaf(w,u.w,P1y);
        w = v.x*F0x; Z2x += w; W2x = fmaf(w,w,W2x); P2x = fmaf(w,v.y,P2x);
        w = v.x*F0y; Z2y += w; W2y = fmaf(w,w,W2y); P2y = fmaf(w,v.y,P2y);
        w = v.z*F1x; Z2x += w; W2x = fmaf(w,w,W2x); P2x = fmaf(w,v.w,P2x);
        w = v.z*F1y; Z2y += w; W2y = fmaf(w,w,W2y); P2y = fmaf(w,v.w,P2y);

        k0 = nk0; k1 = nk1; u = nu; v = nv;
    }
    for (; j < e2; j += 16) {
        float2 nk0 = kp[(size_t)(j+16)*32], nk1 = kp[(size_t)(j+17)*32];
        float4 nv  = ap2[(j+16)>>1];
        pfL1(&kp[(size_t)(j+32)*32]);
        pfL1(&ap2[(j+32)>>1]);

        float F0x = ex2f(qe2x*k0.x), F0y = ex2f(qe2y*k0.y);
        float F1x = ex2f(qe2x*k1.x), F1y = ex2f(qe2y*k1.y);
        float w;
        w = v.x*F0x; Z2x += w; W2x = fmaf(w,w,W2x); P2x = fmaf(w,v.y,P2x);
        w = v.x*F0y; Z2y += w; W2y = fmaf(w,w,W2y); P2y = fmaf(w,v.y,P2y);
        w = v.z*F1x; Z2x += w; W2x = fmaf(w,w,W2x); P2x = fmaf(w,v.w,P2x);
        w = v.z*F1y; Z2y += w; W2y = fmaf(w,w,W2y); P2y = fmaf(w,v.w,P2y);

        k0 = nk0; k1 = nk1; v = nv;
    }

    float2* s2 = (float2*)sm;
    const int base = par*32 + dp;
    s2[0*256 + base] = make_float2(Z1x, Z1y);
    s2[1*256 + base] = make_float2(W1x, W1y);
    s2[2*256 + base] = make_float2(P1x, P1y);
    s2[3*256 + base] = make_float2(Z2x, Z2y);
    s2[4*256 + base] = make_float2(W2x, W2y);
    s2[5*256 + base] = make_float2(P2x, P2y);
    __syncthreads();
    if (tid < 128) {
        const int r = tid >> 6, d = tid & 63;
        const int qb = 3*r;
        float Z = 0.f, W = 0.f, P = 0.f;
#pragma unroll
        for (int pp = 0; pp < 8; pp++) {
            Z += sm[(qb+0)*512 + pp*64 + d];
            W += sm[(qb+1)*512 + pp*64 + d];
            P += sm[(qb+2)*512 + pp*64 + d];
        }
        const int row = r ? row2 : row1;
        float iz = rcpf(Z);
        g_Part[row*HD + d] = fmaf(W*iz, iz, -2.f*P*iz) + g_P2[row];
    }
}

// Single-kernel deterministic reduction: block per head.
__global__ void __launch_bounds__(256) reduce_imp(float* __restrict__ imp)
{
    __shared__ float s[4][64];
    const int h = blockIdx.x, rr = threadIdx.x >> 6, d = threadIdx.x & 63;
    float s0 = 0.f;
#pragma unroll 8
    for (int r = 0; r < 64; ++r)
        s0 += g_Part[(h*SQ + rr*64 + r)*HD + d];
    s[rr][d] = s0;
    __syncthreads();
    if (threadIdx.x < 64)
        imp[h*64 + threadIdx.x] = (s[0][threadIdx.x] + s[1][threadIdx.x])
                                + (s[2][threadIdx.x] + s[3][threadIdx.x]);
}

// ---------------------------------------------------------------------------
extern "C" void kernel_launch(void* const* d_in, const int* in_sizes, int n_in,
                              void* d_out, int out_size)
{
    (void)in_sizes; (void)n_in; (void)out_size;
    const float* hidden   = (const float*)d_in[0];
    const float* residual = (const float*)d_in[1];
    const float* alibi    = (const float*)d_in[2];
    const float* amask    = (const float*)d_in[3];
    const float* Wqkv     = (const float*)d_in[4];
    const float* bqkv     = (const float*)d_in[5];
    const float* Wd       = (const float*)d_in[6];
    const float* bd       = (const float*)d_in[7];
    float* out = (float*)d_out;

    // persistent side stream + fork/join events (created once; capture-legal)
    static cudaStream_t s_imp = nullptr;
    static cudaEvent_t  ev_fork = nullptr, ev_join = nullptr;
    if (s_imp == nullptr) {
        cudaStreamCreateWithFlags(&s_imp, cudaStreamNonBlocking);
        cudaEventCreateWithFlags(&ev_fork, cudaEventDisableTiming);
        cudaEventCreateWithFlags(&ev_join, cudaEventDisableTiming);
    }

    constexpr int SMEM1 = 2*(2*32*72  + 2*BSZ)*4;   // MT=1 DB: 73728
    constexpr int SMEM2 = 2*(2*32*136 + 2*BSZ)*4;   // MT=2 DB: 106496

    cudaFuncSetAttribute(mma_gemm_k<0,2>, cudaFuncAttributeMaxDynamicSharedMemorySize, SMEM2);
    cudaFuncSetAttribute(mma_gemm_k<1,2>, cudaFuncAttributeMaxDynamicSharedMemorySize, SMEM2);
    cudaFuncSetAttribute(mma_gemm_k<2,1>, cudaFuncAttributeMaxDynamicSharedMemorySize, SMEM1);
    cudaFuncSetAttribute(mma_gemm_k<3,1>, cudaFuncAttributeMaxDynamicSharedMemorySize, SMEM1);

    // 1. QKV projection + Q/K/V scatter (best-measured config: MT=2, 96 blocks)
    mma_gemm_k<0,2><<<dim3(48,2,1), 256, SMEM2>>>(hidden, Wqkv, bqkv, nullptr, nullptr);
    // 2. scores S = Q K^T per head
    mma_gemm_k<1,2><<<dim3(4,2,16), 256, SMEM2>>>(nullptr, nullptr, nullptr, nullptr, nullptr);
    // 3. warp-per-row softmax (p, A, P2)
    softmax_k<<<512, 256>>>(alibi, amask);

    // fork: importance chain on side stream, ctx/dense chain on main stream
    cudaEventRecord(ev_fork, 0);
    cudaStreamWaitEvent(s_imp, ev_fork, 0);

    // side: qk importance + deterministic reduce (writes out[SQ*HIDW:])
    importance_k<<<2048, 256, 0, s_imp>>>();
    reduce_imp<<<16, 256, 0, s_imp>>>(out + SQ*HIDW);

    // main: context = P V per head, then dense (+bias+residual; writes out[:SQ*HIDW])
    mma_gemm_k<2,1><<<dim3(1,4,16), 256, SMEM1>>>(nullptr, nullptr, nullptr, nullptr, nullptr);
    mma_gemm_k<3,1><<<dim3(16,4,1), 256, SMEM1>>>(nullptr, Wd, bd, residual, out);

    // join
    cudaEventRecord(ev_join, s_imp);
    cudaStreamWaitEvent(0, ev_join, 0);
}

// round 13
// speedup vs baseline: 1.1636x; 1.1121x over previous
#include <cuda_runtime.h>
#include <cstdint>

#define SQ   256
#define NH   16
#define HD   64
#define HIDW 1024
#define LOG2E 1.4426950408889634f

static __device__ float  g_Q[NH*SQ*HD];
static __device__ float  g_K[NH*SQ*HD + 2048];     // padded: prefetch overshoot
static __device__ float  g_V[NH*SQ*HD];
static __device__ float  g_S[NH*SQ*SQ];
static __device__ float  g_P[NH*SQ*SQ];
static __device__ float2 g_AP[NH*SQ*SQ + 8];
static __device__ float  g_P2[NH*SQ];
static __device__ float  g_Ctx[SQ*HIDW];
static __device__ float  g_Part[NH*SQ*HD];         // [row][d]

__device__ __forceinline__ float ex2f(float x){ float y; asm("ex2.approx.ftz.f32 %0, %1;" : "=f"(y) : "f"(x)); return y; }
__device__ __forceinline__ float rcpf(float x){ float y; asm("rcp.approx.ftz.f32 %0, %1;" : "=f"(y) : "f"(x)); return y; }
__device__ __forceinline__ void pfL1(const void* p){ asm volatile("prefetch.global.L1 [%0];" :: "l"(p)); }

// mask-based tf32 split: hi = x truncated to tf32 mantissa (exactly
// representable), lo = x - hi (exact FADD).  lo is fed to the MMA raw; the
// tensor core truncates its low mantissa bits (error ~2^-21 relative).
__device__ __forceinline__ void split2(float x, float& hi, float& lo){
    hi = __uint_as_float(__float_as_uint(x) & 0xFFFFE000u);
    lo = x - hi;
}

__device__ __forceinline__ void mma8(float* c, const uint32_t* a, const uint32_t* b){
    asm volatile("mma.sync.aligned.m16n8k8.row.col.f32.tf32.tf32.f32 "
        "{%0,%1,%2,%3}, {%4,%5,%6,%7}, {%8,%9}, {%0,%1,%2,%3};"
        : "+f"(c[0]), "+f"(c[1]), "+f"(c[2]), "+f"(c[3])
        : "r"(a[0]), "r"(a[1]), "r"(a[2]), "r"(a[3]), "r"(b[0]), "r"(b[1]));
}

// ---------------------------------------------------------------------------
// tf32-split GEMM, double-buffered smem mainloop (3-term split = fp32-grade).
// MODE 0: fused = hidden @ Wqkv (+bias) -> scatter Q/K/V
// MODE 1: S[h]  = Q[h] @ K[h]^T   (B transposed at staging)
// MODE 2: Ctx   = P[h] @ V[h]
// MODE 3: out   = Ctx @ Wd (+bias+residual)
// ---------------------------------------------------------------------------
#define BSZ (32*72)

template<int MODE, int MT>
__global__ void __launch_bounds__(256, 1) mma_gemm_k(const float* __restrict__ Aext,
                                                     const float* __restrict__ Bext,
                                                     const float* __restrict__ bias,
                                                     const float* __restrict__ resid,
                                                     float* __restrict__ outp)
{
    constexpr int KT  = (MODE==1) ? 64 : (MODE==2) ? 256 : 1024;
    constexpr int NK  = KT/32;
    constexpr int LDA = (MODE==1) ? 64 : (MODE==2) ? 256 : 1024;
    constexpr int LDB = (MODE==0) ? 3072 : (MODE==1) ? 64 : (MODE==2) ? 64 : 1024;
    constexpr int BM  = 64*MT;
    constexpr int AST = BM + 8;
    constexpr int ASZ = 32*AST;
    constexpr int SETSZ = 2*ASZ + 2*BSZ;

    extern __shared__ float sm[];

    const int tid = threadIdx.x, lane = tid & 31, wid = tid >> 5;
    const int wm = wid >> 1, wn = wid & 1;
    const int tig = lane & 3, gid = lane >> 2;
    const int n0 = blockIdx.x*64, m0 = blockIdx.y*BM, z = blockIdx.z;

    const float* Ag; const float* Bg;
    if constexpr (MODE==0)      { Ag = Aext;                  Bg = Bext; }
    else if constexpr (MODE==1) { Ag = g_Q + z*SQ*HD;         Bg = g_K + z*SQ*HD; }
    else if constexpr (MODE==2) { Ag = g_P + (size_t)z*SQ*SQ; Bg = g_V + z*SQ*HD; }
    else                        { Ag = g_Ctx;                 Bg = Bext; }

    const int kqw = tid & 3, mrw = (tid >> 2) & 7, aw = tid >> 5;
    float4 pa[2*MT]; float4 pb[2]; float pbt[8];

    auto loadA = [&](int kt){
#pragma unroll
        for (int mi = 0; mi < MT; mi++)
#pragma unroll
            for (int ki = 0; ki < 2; ki++) {
                int m = aw*8 + mrw + 64*mi, kq = kqw + 4*ki;
                pa[mi*2+ki] = *(const float4*)(Ag + (size_t)(m0+m)*LDA + kt*32 + kq*4);
            }
    };
    auto loadB = [&](int kt){
        if constexpr (MODE==1) {
            int d = tid & 31, jb = (tid >> 5) * 8;
#pragma unroll
            for (int r = 0; r < 8; r++)
                pbt[r] = Bg[(size_t)(n0 + jb + r)*LDB + kt*32 + d];
        } else {
#pragma unroll
            for (int r = 0; r < 2; r++) {
                int idx = tid + 256*r, kr = idx >> 4, nq = idx & 15;
                pb[r] = *(const float4*)(Bg + (size_t)(kt*32 + kr)*LDB + n0 + nq*4);
            }
        }
    };
    auto stage = [&](int buf){
        float* Ah = sm + buf*SETSZ;
        float* Al = Ah + ASZ;
        float* Bh = Ah + 2*ASZ;
        float* Bl = Ah + 2*ASZ + BSZ;
#pragma unroll
        for (int mi = 0; mi < MT; mi++)
#pragma unroll
            for (int ki = 0; ki < 2; ki++) {
                int m = aw*8 + mrw + 64*mi, kq = kqw + 4*ki;
                int mb = m ^ ((kq & 3) << 3);
                float4 v = pa[mi*2+ki];
                float vv[4] = {v.x, v.y, v.z, v.w};
#pragma unroll
                for (int e = 0; e < 4; e++) {
                    float hf, lf;
                    split2(vv[e], hf, lf);
                    Ah[(kq*4+e)*AST + mb] = hf;
                    Al[(kq*4+e)*AST + mb] = lf;
                }
            }
        if constexpr (MODE==1) {
            int d = tid & 31, jb = (tid >> 5) * 8;
            int C = ((d >> 2) & 3) << 3;
#pragma unroll
            for (int r = 0; r < 8; r++) {
                float hf, lf;
                split2(pbt[r], hf, lf);
                int off = d*72 + ((jb + r) ^ C);
                Bh[off] = hf; Bl[off] = lf;
            }
        } else {
#pragma unroll
            for (int r = 0; r < 2; r++) {
                int idx = tid + 256*r, kr = idx >> 4, nq = idx & 15;
                int off = kr*72 + ((nq*4) ^ (((kr >> 2) & 3) << 3));
                float4 v = pb[r];
                float4 h4, l4;
                split2(v.x, h4.x, l4.x);
                split2(v.y, h4.y, l4.y);
                split2(v.z, h4.z, l4.z);
                split2(v.w, h4.w, l4.w);
                *(float4*)(Bh + off) = h4;
                *(float4*)(Bl + off) = l4;
            }
        }
    };

    float acc[MT][4][4];
#pragma unroll
    for (int a = 0; a < MT; a++)
#pragma unroll
        for (int b = 0; b < 4; b++)
#pragma unroll
            for (int c = 0; c < 4; c++) acc[a][b][c] = 0.f;

    auto mmaOn = [&](int buf){
        const uint32_t* Ahu = (const uint32_t*)(sm + buf*SETSZ);
        const uint32_t* Alu = Ahu + ASZ;
        const uint32_t* Bhu = Ahu + 2*ASZ;
        const uint32_t* Blu = Ahu + 2*ASZ + BSZ;
#pragma unroll
        for (int ks = 0; ks < 4; ks++) {
            uint32_t ah[MT][4], al2[MT][4], bh[4][2], bl2[4][2];
            const int kA = ks*8 + tig;
            const int C0 = ((kA >> 2) & 3) << 3;
            const int C1 = (((kA + 4) >> 2) & 3) << 3;
#pragma unroll
            for (int mt = 0; mt < MT; mt++) {
                int m = wm*(16*MT) + mt*16 + gid;
                int mxa = m ^ C0, mya = m ^ C1;
                int i0 = kA*AST, i1 = (kA+4)*AST;
                ah[mt][0]  = Ahu[i0 + mxa];       ah[mt][1]  = Ahu[i0 + (mxa ^ 8)];
                ah[mt][2]  = Ahu[i1 + mya];       ah[mt][3]  = Ahu[i1 + (mya ^ 8)];
                al2[mt][0] = Alu[i0 + mxa];       al2[mt][1] = Alu[i0 + (mxa ^ 8)];
                al2[mt][2] = Alu[i1 + mya];       al2[mt][3] = Alu[i1 + (mya ^ 8)];
            }
#pragma unroll
            for (int nt = 0; nt < 4; nt++) {
                int n = wn*32 + nt*8 + gid;
                bh[nt][0]  = Bhu[kA*72 + (n ^ C0)];
                bh[nt][1]  = Bhu[(kA+4)*72 + (n ^ C1)];
                bl2[nt][0] = Blu[kA*72 + (n ^ C0)];
                bl2[nt][1] = Blu[(kA+4)*72 + (n ^ C1)];
            }
#pragma unroll
            for (int mt = 0; mt < MT; mt++)
#pragma unroll
                for (int nt = 0; nt < 4; nt++) {
                    mma8(acc[mt][nt], ah[mt],  bh[nt]);
                    mma8(acc[mt][nt], ah[mt],  bl2[nt]);
                    mma8(acc[mt][nt], al2[mt], bh[nt]);
                }
        }
    };

    loadA(0); loadB(0);
    stage(0);
    __syncthreads();
    for (int kt = 0; kt < NK; kt++) {
        if (kt + 1 < NK) { loadA(kt+1); loadB(kt+1); }
        mmaOn(kt & 1);
        if (kt + 1 < NK) stage((kt+1) & 1);
        __syncthreads();
    }

#pragma unroll
    for (int mt = 0; mt < MT; mt++) {
        int m = m0 + wm*(16*MT) + mt*16 + gid;
#pragma unroll
        for (int nt = 0; nt < 4; nt++) {
            int n = n0 + wn*32 + nt*8 + tig*2;
            float c0 = acc[mt][nt][0], c1 = acc[mt][nt][1];
            float c2 = acc[mt][nt][2], c3 = acc[mt][nt][3];
            if constexpr (MODE==0) {
                float2 bb = *(const float2*)(bias + n);
                int hh = n / 192, rem = n - hh*192, wch = rem >> 6, d = rem & 63;
                float* base = (wch == 0) ? g_Q : (wch == 1) ? g_K : g_V;
                *(float2*)(base + (size_t)(hh*SQ + m)*HD + d)     = make_float2(c0 + bb.x, c1 + bb.y);
                *(float2*)(base + (size_t)(hh*SQ + m + 8)*HD + d) = make_float2(c2 + bb.x, c3 + bb.y);
            } else if constexpr (MODE==1) {
                *(float2*)(g_S + (size_t)(z*SQ + m)*SQ + n)     = make_float2(c0, c1);
                *(float2*)(g_S + (size_t)(z*SQ + m + 8)*SQ + n) = make_float2(c2, c3);
            } else if constexpr (MODE==2) {
                *(float2*)(g_Ctx + (size_t)m*HIDW + z*HD + n)       = make_float2(c0, c1);
                *(float2*)(g_Ctx + (size_t)(m + 8)*HIDW + z*HD + n) = make_float2(c2, c3);
            } else {
                float2 bb = *(const float2*)(bias + n);
                float2 r0 = *(const float2*)(resid + (size_t)m*HIDW + n);
                float2 r1 = *(const float2*)(resid + (size_t)(m + 8)*HIDW + n);
                *(float2*)(outp + (size_t)m*HIDW + n)       = make_float2(c0 + bb.x + r0.x, c1 + bb.y + r0.y);
                *(float2*)(outp + (size_t)(m + 8)*HIDW + n) = make_float2(c2 + bb.x + r1.x, c3 + bb.y + r1.y);
            }
        }
    }
}

// ---------------------------------------------------------------------------
// Warp-per-row softmax: 8 warps/block, lane owns 8 j's, shfl-only reductions.
// ---------------------------------------------------------------------------
__global__ void __launch_bounds__(256) softmax_k(const float* __restrict__ alibi,
                                                 const float* __restrict__ mask)
{
    const int w = threadIdx.x >> 5, ln = threadIdx.x & 31;
    const int row = blockIdx.x*8 + w;
    const int h = row >> 8, i = row & 255;
    const int j0 = ln*8;

    float4 s0 = *(const float4*)(g_S + (size_t)row*SQ + j0);
    float4 s1 = *(const float4*)(g_S + (size_t)row*SQ + j0 + 4);
    float4 a0 = *(const float4*)(alibi + h*SQ + j0);
    float4 a1 = *(const float4*)(alibi + h*SQ + j0 + 4);
    float4 k0 = *(const float4*)(mask + (size_t)i*SQ + j0);
    float4 k1 = *(const float4*)(mask + (size_t)i*SQ + j0 + 4);

    float sv[8] = {s0.x, s0.y, s0.z, s0.w, s1.x, s1.y, s1.z, s1.w};
    float al[8] = {a0.x, a0.y, a0.z, a0.w, a1.x, a1.y, a1.z, a1.w};
    float mk[8] = {k0.x, k0.y, k0.z, k0.w, k1.x, k1.y, k1.z, k1.w};

    float sc[8];
#pragma unroll
    for (int t = 0; t < 8; t++) sc[t] = fmaf(0.125f, sv[t], al[t]) + mk[t];

    float mx = sc[0];
#pragma unroll
    for (int t = 1; t < 8; t++) mx = fmaxf(mx, sc[t]);
#pragma unroll
    for (int o = 16; o; o >>= 1) mx = fmaxf(mx, __shfl_xor_sync(0xffffffffu, mx, o));

    float e[8], tot = 0.f;
#pragma unroll
    for (int t = 0; t < 8; t++) { e[t] = ex2f((sc[t] - mx) * LOG2E); tot += e[t]; }
#pragma unroll
    for (int o = 16; o; o >>= 1) tot += __shfl_xor_sync(0xffffffffu, tot, o);

    float iz = rcpf(tot);
    float p[8];
#pragma unroll
    for (int t = 0; t < 8; t++) p[t] = e[t] * iz;

    *(float4*)(g_P + (size_t)row*SQ + j0)     = make_float4(p[0], p[1], p[2], p[3]);
    *(float4*)(g_P + (size_t)row*SQ + j0 + 4) = make_float4(p[4], p[5], p[6], p[7]);

    float av[8];
#pragma unroll
    for (int t = 0; t < 8; t++) av[t] = (j0 + t <= i) ? ex2f(sv[t] * (LOG2E/64.f)) : 0.f;

    float4* app = (float4*)(g_AP + (size_t)row*SQ);
    app[ln*4 + 0] = make_float4(av[0], p[0], av[1], p[1]);
    app[ln*4 + 1] = make_float4(av[2], p[2], av[3], p[3]);
    app[ln*4 + 2] = make_float4(av[4], p[4], av[5], p[5]);
    app[ln*4 + 3] = make_float4(av[6], p[6], av[7], p[7]);

    float pq = 0.f;
#pragma unroll
    for (int t = 0; t < 8; t++) pq = fmaf(p[t], p[t], pq);
#pragma unroll
    for (int o = 16; o; o >>= 1) pq += __shfl_xor_sync(0xffffffffu, pq, o);
    if (ln == 0) g_P2[row] = pq;
}

// ---------------------------------------------------------------------------
// qk_importance v5: one block per (h, pair(i1, 255-i1)); 256 threads =
// 32 d-pairs (float2 K) x 8 j-splits.  AP rows cached in SMEM at block start
// (coalesced float4 copy); hot loop reads AP via LDS.  K keeps the depth-1
// register pipeline + L1 prefetch.  Bounds rounded to x16 (A_j==0 masked).
// Deterministic smem combine over the splits.
// ---------------------------------------------------------------------------
__global__ void __launch_bounds__(256) importance_k()
{
    __shared__ float  sm_red[6*512];
    __shared__ float2 sm_ap[2*256];
    const int tid = threadIdx.x;
    const int dp  = tid & 31;
    const int par = tid >> 5;
    const int h   = blockIdx.x >> 7;
    const int i1  = blockIdx.x & 127;
    const int i2  = 255 - i1;
    const int row1 = h*SQ + i1, row2 = h*SQ + i2;

    // cooperative AP -> smem: 256 float4 = both rows
    {
        float4* sap = (float4*)sm_ap;
        if (tid < 128) {
            sap[tid] = ((const float4*)(g_AP + (size_t)row1*SQ))[tid];
        } else {
            sap[tid] = ((const float4*)(g_AP + (size_t)row2*SQ))[tid - 128];
        }
    }

    const float cc = -LOG2E/64.f;
    float2 q1 = *(const float2*)(g_Q + row1*HD + 2*dp);
    float2 q2 = *(const float2*)(g_Q + row2*HD + 2*dp);
    const float qe1x = q1.x*cc, qe1y = q1.y*cc, qe2x = q2.x*cc, qe2y = q2.y*cc;
    const float2* kp   = (const float2*)(g_K + (size_t)h*SQ*HD) + dp;
    const float4* sap1 = (const float4*)sm_ap;         // [0..127]
    const float4* sap2 = (const float4*)sm_ap + 128;   // [0..127]

    float Z1x=0.f, Z1y=0.f, W1x=0.f, W1y=0.f, P1x=0.f, P1y=0.f;
    float Z2x=0.f, Z2y=0.f, W2x=0.f, W2y=0.f, P2x=0.f, P2y=0.f;

    const int e1 = (i1 + 16) & ~15;
    const int e2 = (i2 + 16) & ~15;
    int j = 2*par;

    float2 k0 = kp[(size_t)j*32], k1 = kp[(size_t)(j+1)*32];
    __syncthreads();                          // AP smem ready

    for (; j < e1; j += 16) {
        float2 nk0 = kp[(size_t)(j+16)*32], nk1 = kp[(size_t)(j+17)*32];
        pfL1(&kp[(size_t)(j+32)*32]);
        float4 u = sap1[j>>1];
        float4 v = sap2[j>>1];

        float E0x = ex2f(qe1x*k0.x), E0y = ex2f(qe1y*k0.y);
        float E1x = ex2f(qe1x*k1.x), E1y = ex2f(qe1y*k1.y);
        float F0x = ex2f(qe2x*k0.x), F0y = ex2f(qe2y*k0.y);
        float F1x = ex2f(qe2x*k1.x), F1y = ex2f(qe2y*k1.y);
        float w;
        w = u.x*E0x; Z1x += w; W1x = fmaf(w,w,W1x); P1x = fmaf(w,u.y,P1x);
        w = u.x*E0y; Z1y += w; W1y = fmaf(w,w,W1y); P1y = fmaf(w,u.y,P1y);
        w = u.z*E1x; Z1x += w; W1x = fmaf(w,w,W1x); P1x = fmaf(w,u.w,P1x);
        w = u.z*E1y; Z1y += w; W1y = fmaf(w,w,W1y); P1y = fmaf(w,u.w,P1y);
        w = v.x*F0x; Z2x += w; W2x = fmaf(w,w,W2x); P2x = fmaf(w,v.y,P2x);
        w = v.x*F0y; Z2y += w; W2y = fmaf(w,w,W2y); P2y = fmaf(w,v.y,P2y);
        w = v.z*F1x; Z2x += w; W2x = fmaf(w,w,W2x); P2x = fmaf(w,v.w,P2x);
        w = v.z*F1y; Z2y += w; W2y = fmaf(w,w,W2y); P2y = fmaf(w,v.w,P2y);

        k0 = nk0; k1 = nk1;
    }
    for (; j < e2; j += 16) {
        float2 nk0 = kp[(size_t)(j+16)*32], nk1 = kp[(size_t)(j+17)*32];
        pfL1(&kp[(size_t)(j+32)*32]);
        float4 v = sap2[j>>1];

        float F0x = ex2f(qe2x*k0.x), F0y = ex2f(qe2y*k0.y);
        float F1x = ex2f(qe2x*k1.x), F1y = ex2f(qe2y*k1.y);
        float w;
        w = v.x*F0x; Z2x += w; W2x = fmaf(w,w,W2x); P2x = fmaf(w,v.y,P2x);
        w = v.x*F0y; Z2y += w; W2y = fmaf(w,w,W2y); P2y = fmaf(w,v.y,P2y);
        w = v.z*F1x; Z2x += w; W2x = fmaf(w,w,W2x); P2x = fmaf(w,v.w,P2x);
        w = v.z*F1y; Z2y += w; W2y = fmaf(w,w,W2y); P2y = fmaf(w,v.w,P2y);

        k0 = nk0; k1 = nk1;
    }

    float2* s2 = (float2*)sm_red;
    const int base = par*32 + dp;
    s2[0*256 + base] = make_float2(Z1x, Z1y);
    s2[1*256 + base] = make_float2(W1x, W1y);
    s2[2*256 + base] = make_float2(P1x, P1y);
    s2[3*256 + base] = make_float2(Z2x, Z2y);
    s2[4*256 + base] = make_float2(W2x, W2y);
    s2[5*256 + base] = make_float2(P2x, P2y);
    __syncthreads();
    if (tid < 128) {
        const int r = tid >> 6, d = tid & 63;
        const int qb = 3*r;
        float Z = 0.f, W = 0.f, P = 0.f;
#pragma unroll
        for (int pp = 0; pp < 8; pp++) {
            Z += sm_red[(qb+0)*512 + pp*64 + d];
            W += sm_red[(qb+1)*512 + pp*64 + d];
            P += sm_red[(qb+2)*512 + pp*64 + d];
        }
        const int row = r ? row2 : row1;
        float iz = rcpf(Z);
        g_Part[row*HD + d] = fmaf(W*iz, iz, -2.f*P*iz) + g_P2[row];
    }
}

// Single-kernel deterministic reduction: block per head.
__global__ void __launch_bounds__(256) reduce_imp(float* __restrict__ imp)
{
    __shared__ float s[4][64];
    const int h = blockIdx.x, rr = threadIdx.x >> 6, d = threadIdx.x & 63;
    float s0 = 0.f;
#pragma unroll 8
    for (int r = 0; r < 64; ++r)
        s0 += g_Part[(h*SQ + rr*64 + r)*HD + d];
    s[rr][d] = s0;
    __syncthreads();
    if (threadIdx.x < 64)
        imp[h*64 + threadIdx.x] = (s[0][threadIdx.x] + s[1][threadIdx.x])
                                + (s[2][threadIdx.x] + s[3][threadIdx.x]);
}

// ---------------------------------------------------------------------------
extern "C" void kernel_launch(void* const* d_in, const int* in_sizes, int n_in,
                              void* d_out, int out_size)
{
    (void)in_sizes; (void)n_in; (void)out_size;
    const float* hidden   = (const float*)d_in[0];
    const float* residual = (const float*)d_in[1];
    const float* alibi    = (const float*)d_in[2];
    const float* amask    = (const float*)d_in[3];
    const float* Wqkv     = (const float*)d_in[4];
    const float* bqkv     = (const float*)d_in[5];
    const float* Wd       = (const float*)d_in[6];
    const float* bd       = (const float*)d_in[7];
    float* out = (float*)d_out;

    // persistent side stream + fork/join events (created once; capture-legal)
    static cudaStream_t s_imp = nullptr;
    static cudaEvent_t  ev_fork = nullptr, ev_join = nullptr;
    if (s_imp == nullptr) {
        cudaStreamCreateWithFlags(&s_imp, cudaStreamNonBlocking);
        cudaEventCreateWithFlags(&ev_fork, cudaEventDisableTiming);
        cudaEventCreateWithFlags(&ev_join, cudaEventDisableTiming);
    }

    constexpr int SMEM1 = 2*(2*32*72  + 2*BSZ)*4;   // MT=1 DB: 73728
    constexpr int SMEM2 = 2*(2*32*136 + 2*BSZ)*4;   // MT=2 DB: 106496

    cudaFuncSetAttribute(mma_gemm_k<0,2>, cudaFuncAttributeMaxDynamicSharedMemorySize, SMEM2);
    cudaFuncSetAttribute(mma_gemm_k<1,2>, cudaFuncAttributeMaxDynamicSharedMemorySize, SMEM2);
    cudaFuncSetAttribute(mma_gemm_k<2,1>, cudaFuncAttributeMaxDynamicSharedMemorySize, SMEM1);
    cudaFuncSetAttribute(mma_gemm_k<3,1>, cudaFuncAttributeMaxDynamicSharedMemorySize, SMEM1);

    // 1. QKV projection + Q/K/V scatter (MT=2, 96 blocks — measured best)
    mma_gemm_k<0,2><<<dim3(48,2,1), 256, SMEM2>>>(hidden, Wqkv, bqkv, nullptr, nullptr);
    // 2. scores S = Q K^T per head
    mma_gemm_k<1,2><<<dim3(4,2,16), 256, SMEM2>>>(nullptr, nullptr, nullptr, nullptr, nullptr);
    // 3. warp-per-row softmax (p, A, P2)
    softmax_k<<<512, 256>>>(alibi, amask);

    // fork: importance chain on side stream, ctx/dense chain on main stream
    cudaEventRecord(ev_fork, 0);
    cudaStreamWaitEvent(s_imp, ev_fork, 0);

    // side: qk importance + deterministic reduce (writes out[SQ*HIDW:])
    importance_k<<<2048, 256, 0, s_imp>>>();
    reduce_imp<<<16, 256, 0, s_imp>>>(out + SQ*HIDW);

    // main: context = P V per head, then dense (+bias+residual; writes out[:SQ*HIDW])
    mma_gemm_k<2,1><<<dim3(1,4,16), 256, SMEM1>>>(nullptr, nullptr, nullptr, nullptr, nullptr);
    mma_gemm_k<3,1><<<dim3(16,4,1), 256, SMEM1>>>(nullptr, Wd, bd, residual, out);

    // join
    cudaEventRecord(ev_join, s_imp);
    cudaStreamWaitEvent(0, ev_join, 0);
}

// round 14
// speedup vs baseline: 1.2832x; 1.1027x over previous
#include <cuda_runtime.h>
#include <cstdint>

#define SQ   256
#define NH   16
#define HD   64
#define HIDW 1024
#define LOG2E 1.4426950408889634f

static __device__ float  g_Q[NH*SQ*HD];
static __device__ float  g_K[NH*SQ*HD + 2048];     // padded: prefetch overshoot
static __device__ float  g_V[NH*SQ*HD];
static __device__ float  g_S[NH*SQ*SQ];
static __device__ float  g_P[NH*SQ*SQ];
static __device__ float2 g_AP[NH*SQ*SQ + 8];
static __device__ float  g_P2[NH*SQ];
static __device__ float  g_Ctx[SQ*HIDW];
static __device__ float  g_Part[NH*SQ*HD];         // [row][d]

__device__ __forceinline__ float ex2f(float x){ float y; asm("ex2.approx.ftz.f32 %0, %1;" : "=f"(y) : "f"(x)); return y; }
__device__ __forceinline__ float rcpf(float x){ float y; asm("rcp.approx.ftz.f32 %0, %1;" : "=f"(y) : "f"(x)); return y; }
__device__ __forceinline__ void pfL1(const void* p){ asm volatile("prefetch.global.L1 [%0];" :: "l"(p)); }

// mask-based tf32 split: hi = x truncated to tf32 mantissa (exactly
// representable), lo = x - hi (exact FADD).  lo fed raw to MMA (HW truncates).
__device__ __forceinline__ void split2(float x, float& hi, float& lo){
    hi = __uint_as_float(__float_as_uint(x) & 0xFFFFE000u);
    lo = x - hi;
}

__device__ __forceinline__ void mma8(float* c, const uint32_t* a, const uint32_t* b){
    asm volatile("mma.sync.aligned.m16n8k8.row.col.f32.tf32.tf32.f32 "
        "{%0,%1,%2,%3}, {%4,%5,%6,%7}, {%8,%9}, {%0,%1,%2,%3};"
        : "+f"(c[0]), "+f"(c[1]), "+f"(c[2]), "+f"(c[3])
        : "r"(a[0]), "r"(a[1]), "r"(a[2]), "r"(a[3]), "r"(b[0]), "r"(b[1]));
}

// ---------------------------------------------------------------------------
// tf32-split GEMM, double-buffered smem mainloop.
// NT3=1: 3-term split (hi·hi + hi·lo + lo·hi) — fp32-grade; used where the
//        output feeds the error-amplifying importance path (QKV, scores).
// NT3=0: 2-term (a·bh + a·bl), A staged raw (HW-truncated) — ~2^-12 rel err,
//        used for ctx/dense whose output feeds `out` directly (no amplification).
// MODE 0: fused = hidden @ Wqkv (+bias) -> scatter Q/K/V
// MODE 1: S[h]  = Q[h] @ K[h]^T   (B transposed at staging)
// MODE 2: Ctx   = P[h] @ V[h]
// MODE 3: out   = Ctx @ Wd (+bias+residual)
// ---------------------------------------------------------------------------
#define BSZ (32*72)

template<int MODE, int MT, int NT3>
__global__ void __launch_bounds__(256, 1) mma_gemm_k(const float* __restrict__ Aext,
                                                     const float* __restrict__ Bext,
                                                     const float* __restrict__ bias,
                                                     const float* __restrict__ resid,
                                                     float* __restrict__ outp)
{
    constexpr int KT  = (MODE==1) ? 64 : (MODE==2) ? 256 : 1024;
    constexpr int NK  = KT/32;
    constexpr int LDA = (MODE==1) ? 64 : (MODE==2) ? 256 : 1024;
    constexpr int LDB = (MODE==0) ? 3072 : (MODE==1) ? 64 : (MODE==2) ? 64 : 1024;
    constexpr int BM  = 64*MT;
    constexpr int AST = BM + 8;
    constexpr int ASZ = 32*AST;
    constexpr int NA  = NT3 ? 2 : 1;               // A planes (hi[,lo])
    constexpr int SETSZ = NA*ASZ + 2*BSZ;

    extern __shared__ float sm[];

    const int tid = threadIdx.x, lane = tid & 31, wid = tid >> 5;
    const int wm = wid >> 1, wn = wid & 1;
    const int tig = lane & 3, gid = lane >> 2;
    const int n0 = blockIdx.x*64, m0 = blockIdx.y*BM, z = blockIdx.z;

    const float* Ag; const float* Bg;
    if constexpr (MODE==0)      { Ag = Aext;                  Bg = Bext; }
    else if constexpr (MODE==1) { Ag = g_Q + z*SQ*HD;         Bg = g_K + z*SQ*HD; }
    else if constexpr (MODE==2) { Ag = g_P + (size_t)z*SQ*SQ; Bg = g_V + z*SQ*HD; }
    else                        { Ag = g_Ctx;                 Bg = Bext; }

    const int kqw = tid & 3, mrw = (tid >> 2) & 7, aw = tid >> 5;
    float4 pa[2*MT]; float4 pb[2]; float pbt[8];

    auto loadA = [&](int kt){
#pragma unroll
        for (int mi = 0; mi < MT; mi++)
#pragma unroll
            for (int ki = 0; ki < 2; ki++) {
                int m = aw*8 + mrw + 64*mi, kq = kqw + 4*ki;
                pa[mi*2+ki] = *(const float4*)(Ag + (size_t)(m0+m)*LDA + kt*32 + kq*4);
            }
    };
    auto loadB = [&](int kt){
        if constexpr (MODE==1) {
            int d = tid & 31, jb = (tid >> 5) * 8;
#pragma unroll
            for (int r = 0; r < 8; r++)
                pbt[r] = Bg[(size_t)(n0 + jb + r)*LDB + kt*32 + d];
        } else {
#pragma unroll
            for (int r = 0; r < 2; r++) {
                int idx = tid + 256*r, kr = idx >> 4, nq = idx & 15;
                pb[r] = *(const float4*)(Bg + (size_t)(kt*32 + kr)*LDB + n0 + nq*4);
            }
        }
    };
    auto stage = [&](int buf){
        float* Ah = sm + buf*SETSZ;
        float* Al = Ah + ASZ;                      // only used when NT3
        float* Bh = Ah + NA*ASZ;
        float* Bl = Bh + BSZ;
#pragma unroll
        for (int mi = 0; mi < MT; mi++)
#pragma unroll
            for (int ki = 0; ki < 2; ki++) {
                int m = aw*8 + mrw + 64*mi, kq = kqw + 4*ki;
                int mb = m ^ ((kq & 3) << 3);
                float4 v = pa[mi*2+ki];
                float vv[4] = {v.x, v.y, v.z, v.w};
#pragma unroll
                for (int e = 0; e < 4; e++) {
                    if constexpr (NT3) {
                        float hf, lf;
                        split2(vv[e], hf, lf);
                        Ah[(kq*4+e)*AST + mb] = hf;
                        Al[(kq*4+e)*AST + mb] = lf;
                    } else {
                        Ah[(kq*4+e)*AST + mb] = vv[e];   // raw; HW truncates
                    }
                }
            }
        if constexpr (MODE==1) {
            int d = tid & 31, jb = (tid >> 5) * 8;
            int C = ((d >> 2) & 3) << 3;
#pragma unroll
            for (int r = 0; r < 8; r++) {
                float hf, lf;
                split2(pbt[r], hf, lf);
                int off = d*72 + ((jb + r) ^ C);
                Bh[off] = hf; Bl[off] = lf;
            }
        } else {
#pragma unroll
            for (int r = 0; r < 2; r++) {
                int idx = tid + 256*r, kr = idx >> 4, nq = idx & 15;
                int off = kr*72 + ((nq*4) ^ (((kr >> 2) & 3) << 3));
                float4 v = pb[r];
                float4 h4, l4;
                split2(v.x, h4.x, l4.x);
                split2(v.y, h4.y, l4.y);
                split2(v.z, h4.z, l4.z);
                split2(v.w, h4.w, l4.w);
                *(float4*)(Bh + off) = h4;
                *(float4*)(Bl + off) = l4;
            }
        }
    };

    float acc[MT][4][4];
#pragma unroll
    for (int a = 0; a < MT; a++)
#pragma unroll
        for (int b = 0; b < 4; b++)
#pragma unroll
            for (int c = 0; c < 4; c++) acc[a][b][c] = 0.f;

    auto mmaOn = [&](int buf){
        const uint32_t* Ahu = (const uint32_t*)(sm + buf*SETSZ);
        const uint32_t* Alu = Ahu + ASZ;
        const uint32_t* Bhu = Ahu + NA*ASZ;
        const uint32_t* Blu = Bhu + BSZ;
#pragma unroll
        for (int ks = 0; ks < 4; ks++) {
            uint32_t ah[MT][4], al2[MT][4], bh[4][2], bl2[4][2];
            const int kA = ks*8 + tig;
            const int C0 = ((kA >> 2) & 3) << 3;
            const int C1 = (((kA + 4) >> 2) & 3) << 3;
#pragma unroll
            for (int mt = 0; mt < MT; mt++) {
                int m = wm*(16*MT) + mt*16 + gid;
                int mxa = m ^ C0, mya = m ^ C1;
                int i0 = kA*AST, i1 = (kA+4)*AST;
                ah[mt][0]  = Ahu[i0 + mxa];       ah[mt][1]  = Ahu[i0 + (mxa ^ 8)];
                ah[mt][2]  = Ahu[i1 + mya];       ah[mt][3]  = Ahu[i1 + (mya ^ 8)];
                if constexpr (NT3) {
                    al2[mt][0] = Alu[i0 + mxa];   al2[mt][1] = Alu[i0 + (mxa ^ 8)];
                    al2[mt][2] = Alu[i1 + mya];   al2[mt][3] = Alu[i1 + (mya ^ 8)];
                }
            }
#pragma unroll
            for (int nt = 0; nt < 4; nt++) {
                int n = wn*32 + nt*8 + gid;
                bh[nt][0]  = Bhu[kA*72 + (n ^ C0)];
                bh[nt][1]  = Bhu[(kA+4)*72 + (n ^ C1)];
                bl2[nt][0] = Blu[kA*72 + (n ^ C0)];
                bl2[nt][1] = Blu[(kA+4)*72 + (n ^ C1)];
            }
#pragma unroll
            for (int mt = 0; mt < MT; mt++)
#pragma unroll
                for (int nt = 0; nt < 4; nt++) {
                    mma8(acc[mt][nt], ah[mt],  bh[nt]);
                    mma8(acc[mt][nt], ah[mt],  bl2[nt]);
                    if constexpr (NT3)
                        mma8(acc[mt][nt], al2[mt], bh[nt]);
                }
        }
    };

    loadA(0); loadB(0);
    stage(0);
    __syncthreads();
    for (int kt = 0; kt < NK; kt++) {
        if (kt + 1 < NK) { loadA(kt+1); loadB(kt+1); }
        mmaOn(kt & 1);
        if (kt + 1 < NK) stage((kt+1) & 1);
        __syncthreads();
    }

#pragma unroll
    for (int mt = 0; mt < MT; mt++) {
        int m = m0 + wm*(16*MT) + mt*16 + gid;
#pragma unroll
        for (int nt = 0; nt < 4; nt++) {
            int n = n0 + wn*32 + nt*8 + tig*2;
            float c0 = acc[mt][nt][0], c1 = acc[mt][nt][1];
            float c2 = acc[mt][nt][2], c3 = acc[mt][nt][3];
            if constexpr (MODE==0) {
                float2 bb = *(const float2*)(bias + n);
                int hh = n / 192, rem = n - hh*192, wch = rem >> 6, d = rem & 63;
                float* base = (wch == 0) ? g_Q : (wch == 1) ? g_K : g_V;
                *(float2*)(base + (size_t)(hh*SQ + m)*HD + d)     = make_float2(c0 + bb.x, c1 + bb.y);
                *(float2*)(base + (size_t)(hh*SQ + m + 8)*HD + d) = make_float2(c2 + bb.x, c3 + bb.y);
            } else if constexpr (MODE==1) {
                *(float2*)(g_S + (size_t)(z*SQ + m)*SQ + n)     = make_float2(c0, c1);
                *(float2*)(g_S + (size_t)(z*SQ + m + 8)*SQ + n) = make_float2(c2, c3);
            } else if constexpr (MODE==2) {
                *(float2*)(g_Ctx + (size_t)m*HIDW + z*HD + n)       = make_float2(c0, c1);
                *(float2*)(g_Ctx + (size_t)(m + 8)*HIDW + z*HD + n) = make_float2(c2, c3);
            } else {
                float2 bb = *(const float2*)(bias + n);
                float2 r0 = *(const float2*)(resid + (size_t)m*HIDW + n);
                float2 r1 = *(const float2*)(resid + (size_t)(m + 8)*HIDW + n);
                *(float2*)(outp + (size_t)m*HIDW + n)       = make_float2(c0 + bb.x + r0.x, c1 + bb.y + r0.y);
                *(float2*)(outp + (size_t)(m + 8)*HIDW + n) = make_float2(c2 + bb.x + r1.x, c3 + bb.y + r1.y);
            }
        }
    }
}

// ---------------------------------------------------------------------------
// Warp-per-row softmax: 8 warps/block, lane owns 8 j's, shfl-only reductions.
// ---------------------------------------------------------------------------
__global__ void __launch_bounds__(256) softmax_k(const float* __restrict__ alibi,
                                                 const float* __restrict__ mask)
{
    const int w = threadIdx.x >> 5, ln = threadIdx.x & 31;
    const int row = blockIdx.x*8 + w;
    const int h = row >> 8, i = row & 255;
    const int j0 = ln*8;

    float4 s0 = *(const float4*)(g_S + (size_t)row*SQ + j0);
    float4 s1 = *(const float4*)(g_S + (size_t)row*SQ + j0 + 4);
    float4 a0 = *(const float4*)(alibi + h*SQ + j0);
    float4 a1 = *(const float4*)(alibi + h*SQ + j0 + 4);
    float4 k0 = *(const float4*)(mask + (size_t)i*SQ + j0);
    float4 k1 = *(const float4*)(mask + (size_t)i*SQ + j0 + 4);

    float sv[8] = {s0.x, s0.y, s0.z, s0.w, s1.x, s1.y, s1.z, s1.w};
    float al[8] = {a0.x, a0.y, a0.z, a0.w, a1.x, a1.y, a1.z, a1.w};
    float mk[8] = {k0.x, k0.y, k0.z, k0.w, k1.x, k1.y, k1.z, k1.w};

    float sc[8];
#pragma unroll
    for (int t = 0; t < 8; t++) sc[t] = fmaf(0.125f, sv[t], al[t]) + mk[t];

    float mx = sc[0];
#pragma unroll
    for (int t = 1; t < 8; t++) mx = fmaxf(mx, sc[t]);
#pragma unroll
    for (int o = 16; o; o >>= 1) mx = fmaxf(mx, __shfl_xor_sync(0xffffffffu, mx, o));

    float e[8], tot = 0.f;
#pragma unroll
    for (int t = 0; t < 8; t++) { e[t] = ex2f((sc[t] - mx) * LOG2E); tot += e[t]; }
#pragma unroll
    for (int o = 16; o; o >>= 1) tot += __shfl_xor_sync(0xffffffffu, tot, o);

    float iz = rcpf(tot);
    float p[8];
#pragma unroll
    for (int t = 0; t < 8; t++) p[t] = e[t] * iz;

    *(float4*)(g_P + (size_t)row*SQ + j0)     = make_float4(p[0], p[1], p[2], p[3]);
    *(float4*)(g_P + (size_t)row*SQ + j0 + 4) = make_float4(p[4], p[5], p[6], p[7]);

    float av[8];
#pragma unroll
    for (int t = 0; t < 8; t++) av[t] = (j0 + t <= i) ? ex2f(sv[t] * (LOG2E/64.f)) : 0.f;

    float4* app = (float4*)(g_AP + (size_t)row*SQ);
    app[ln*4 + 0] = make_float4(av[0], p[0], av[1], p[1]);
    app[ln*4 + 1] = make_float4(av[2], p[2], av[3], p[3]);
    app[ln*4 + 2] = make_float4(av[4], p[4], av[5], p[5]);
    app[ln*4 + 3] = make_float4(av[6], p[6], av[7], p[7]);

    float pq = 0.f;
#pragma unroll
    for (int t = 0; t < 8; t++) pq = fmaf(p[t], p[t], pq);
#pragma unroll
    for (int o = 16; o; o >>= 1) pq += __shfl_xor_sync(0xffffffffu, pq, o);
    if (ln == 0) g_P2[row] = pq;
}

// ---------------------------------------------------------------------------
// qk_importance v5 (unchanged from R13 win): block per (h, pair(i1,255-i1));
// 32 d-pairs x 8 j-splits; AP cached in smem; K depth-1 register pipeline.
// ---------------------------------------------------------------------------
__global__ void __launch_bounds__(256) importance_k()
{
    __shared__ float  sm_red[6*512];
    __shared__ float2 sm_ap[2*256];
    const int tid = threadIdx.x;
    const int dp  = tid & 31;
    const int par = tid >> 5;
    const int h   = blockIdx.x >> 7;
    const int i1  = blockIdx.x & 127;
    const int i2  = 255 - i1;
    const int row1 = h*SQ + i1, row2 = h*SQ + i2;

    {
        float4* sap = (float4*)sm_ap;
        if (tid < 128) {
            sap[tid] = ((const float4*)(g_AP + (size_t)row1*SQ))[tid];
        } else {
            sap[tid] = ((const float4*)(g_AP + (size_t)row2*SQ))[tid - 128];
        }
    }

    const float cc = -LOG2E/64.f;
    float2 q1 = *(const float2*)(g_Q + row1*HD + 2*dp);
    float2 q2 = *(const float2*)(g_Q + row2*HD + 2*dp);
    const float qe1x = q1.x*cc, qe1y = q1.y*cc, qe2x = q2.x*cc, qe2y = q2.y*cc;
    const float2* kp   = (const float2*)(g_K + (size_t)h*SQ*HD) + dp;
    const float4* sap1 = (const float4*)sm_ap;
    const float4* sap2 = (const float4*)sm_ap + 128;

    float Z1x=0.f, Z1y=0.f, W1x=0.f, W1y=0.f, P1x=0.f, P1y=0.f;
    float Z2x=0.f, Z2y=0.f, W2x=0.f, W2y=0.f, P2x=0.f, P2y=0.f;

    const int e1 = (i1 + 16) & ~15;
    const int e2 = (i2 + 16) & ~15;
    int j = 2*par;

    float2 k0 = kp[(size_t)j*32], k1 = kp[(size_t)(j+1)*32];
    __syncthreads();

    for (; j < e1; j += 16) {
        float2 nk0 = kp[(size_t)(j+16)*32], nk1 = kp[(size_t)(j+17)*32];
        pfL1(&kp[(size_t)(j+32)*32]);
        float4 u = sap1[j>>1];
        float4 v = sap2[j>>1];

        float E0x = ex2f(qe1x*k0.x), E0y = ex2f(qe1y*k0.y);
        float E1x = ex2f(qe1x*k1.x), E1y = ex2f(qe1y*k1.y);
        float F0x = ex2f(qe2x*k0.x), F0y = ex2f(qe2y*k0.y);
        float F1x = ex2f(qe2x*k1.x), F1y = ex2f(qe2y*k1.y);
        float w;
        w = u.x*E0x; Z1x += w; W1x = fmaf(w,w,W1x); P1x = fmaf(w,u.y,P1x);
        w = u.x*E0y; Z1y += w; W1y = fmaf(w,w,W1y); P1y = fmaf(w,u.y,P1y);
        w = u.z*E1x; Z1x += w; W1x = fmaf(w,w,W1x); P1x = fmaf(w,u.w,P1x);
        w = u.z*E1y; Z1y += w; W1y = fmaf(w,w,W1y); P1y = fmaf(w,u.w,P1y);
        w = v.x*F0x; Z2x += w; W2x = fmaf(w,w,W2x); P2x = fmaf(w,v.y,P2x);
        w = v.x*F0y; Z2y += w; W2y = fmaf(w,w,W2y); P2y = fmaf(w,v.y,P2y);
        w = v.z*F1x; Z2x += w; W2x = fmaf(w,w,W2x); P2x = fmaf(w,v.w,P2x);
        w = v.z*F1y; Z2y += w; W2y = fmaf(w,w,W2y); P2y = fmaf(w,v.w,P2y);

        k0 = nk0; k1 = nk1;
    }
    for (; j < e2; j += 16) {
        float2 nk0 = kp[(size_t)(j+16)*32], nk1 = kp[(size_t)(j+17)*32];
        pfL1(&kp[(size_t)(j+32)*32]);
        float4 v = sap2[j>>1];

        float F0x = ex2f(qe2x*k0.x), F0y = ex2f(qe2y*k0.y);
        float F1x = ex2f(qe2x*k1.x), F1y = ex2f(qe2y*k1.y);
        float w;
        w = v.x*F0x; Z2x += w; W2x = fmaf(w,w,W2x); P2x = fmaf(w,v.y,P2x);
        w = v.x*F0y; Z2y += w; W2y = fmaf(w,w,W2y); P2y = fmaf(w,v.y,P2y);
        w = v.z*F1x; Z2x += w; W2x = fmaf(w,w,W2x); P2x = fmaf(w,v.w,P2x);
        w = v.z*F1y; Z2y += w; W2y = fmaf(w,w,W2y); P2y = fmaf(w,v.w,P2y);

        k0 = nk0; k1 = nk1;
    }

    float2* s2 = (float2*)sm_red;
    const int base = par*32 + dp;
    s2[0*256 + base] = make_float2(Z1x, Z1y);
    s2[1*256 + base] = make_float2(W1x, W1y);
    s2[2*256 + base] = make_float2(P1x, P1y);
    s2[3*256 + base] = make_float2(Z2x, Z2y);
    s2[4*256 + base] = make_float2(W2x, W2y);
    s2[5*256 + base] = make_float2(P2x, P2y);
    __syncthreads();
    if (tid < 128) {
        const int r = tid >> 6, d = tid & 63;
        const int qb = 3*r;
        float Z = 0.f, W = 0.f, P = 0.f;
#pragma unroll
        for (int pp = 0; pp < 8; pp++) {
            Z += sm_red[(qb+0)*512 + pp*64 + d];
            W += sm_red[(qb+1)*512 + pp*64 + d];
            P += sm_red[(qb+2)*512 + pp*64 + d];
        }
        const int row = r ? row2 : row1;
        float iz = rcpf(Z);
        g_Part[row*HD + d] = fmaf(W*iz, iz, -2.f*P*iz) + g_P2[row];
    }
}

// Single-kernel deterministic reduction: block per head.
__global__ void __launch_bounds__(256) reduce_imp(float* __restrict__ imp)
{
    __shared__ float s[4][64];
    const int h = blockIdx.x, rr = threadIdx.x >> 6, d = threadIdx.x & 63;
    float s0 = 0.f;
#pragma unroll 8
    for (int r = 0; r < 64; ++r)
        s0 += g_Part[(h*SQ + rr*64 + r)*HD + d];
    s[rr][d] = s0;
    __syncthreads();
    if (threadIdx.x < 64)
        imp[h*64 + threadIdx.x] = (s[0][threadIdx.x] + s[1][threadIdx.x])
                                + (s[2][threadIdx.x] + s[3][threadIdx.x]);
}

// ---------------------------------------------------------------------------
extern "C" void kernel_launch(void* const* d_in, const int* in_sizes, int n_in,
                              void* d_out, int out_size)
{
    (void)in_sizes; (void)n_in; (void)out_size;
    const float* hidden   = (const float*)d_in[0];
    const float* residual = (const float*)d_in[1];
    const float* alibi    = (const float*)d_in[2];
    const float* amask    = (const float*)d_in[3];
    const float* Wqkv     = (const float*)d_in[4];
    const float* bqkv     = (const float*)d_in[5];
    const float* Wd       = (const float*)d_in[6];
    const float* bd       = (const float*)d_in[7];
    float* out = (float*)d_out;

    // persistent side stream + fork/join events (created once; capture-legal)
    static cudaStream_t s_imp = nullptr;
    static cudaEvent_t  ev_fork = nullptr, ev_join = nullptr;
    if (s_imp == nullptr) {
        cudaStreamCreateWithFlags(&s_imp, cudaStreamNonBlocking);
        cudaEventCreateWithFlags(&ev_fork, cudaEventDisableTiming);
        cudaEventCreateWithFlags(&ev_join, cudaEventDisableTiming);
    }

    constexpr int SMEM2  = 2*(2*32*136 + 2*BSZ)*4;  // MT=2, NT3=1: 106496
    constexpr int SMEM1S = 2*(1*32*72  + 2*BSZ)*4;  // MT=1, NT3=0: 55296

    cudaFuncSetAttribute(mma_gemm_k<0,2,1>, cudaFuncAttributeMaxDynamicSharedMemorySize, SMEM2);
    cudaFuncSetAttribute(mma_gemm_k<1,2,1>, cudaFuncAttributeMaxDynamicSharedMemorySize, SMEM2);
    cudaFuncSetAttribute(mma_gemm_k<2,1,0>, cudaFuncAttributeMaxDynamicSharedMemorySize, SMEM1S);
    cudaFuncSetAttribute(mma_gemm_k<3,1,0>, cudaFuncAttributeMaxDynamicSharedMemorySize, SMEM1S);

    // 1. QKV projection + Q/K/V scatter (3-term: feeds importance path)
    mma_gemm_k<0,2,1><<<dim3(48,2,1), 256, SMEM2>>>(hidden, Wqkv, bqkv, nullptr, nullptr);
    // 2. scores S = Q K^T per head (3-term: feeds importance path)
    mma_gemm_k<1,2,1><<<dim3(4,2,16), 256, SMEM2>>>(nullptr, nullptr, nullptr, nullptr, nullptr);
    // 3. warp-per-row softmax (p, A, P2)
    softmax_k<<<512, 256>>>(alibi, amask);

    // fork: importance chain on side stream, ctx/dense chain on main stream
    cudaEventRecord(ev_fork, 0);
    cudaStreamWaitEvent(s_imp, ev_fork, 0);

    // side: qk importance + deterministic reduce (writes out[SQ*HIDW:])
    importance_k<<<2048, 256, 0, s_imp>>>();
    reduce_imp<<<16, 256, 0, s_imp>>>(out + SQ*HIDW);

    // main: context = P V (2-term: linear path), then dense (2-term)
    mma_gemm_k<2,1,0><<<dim3(1,4,16), 256, SMEM1S>>>(nullptr, nullptr, nullptr, nullptr, nullptr);
    mma_gemm_k<3,1,0><<<dim3(16,4,1), 256, SMEM1S>>>(nullptr, Wd, bd, residual, out);

    // join
    cudaEventRecord(ev_join, s_imp);
    cudaStreamWaitEvent(0, ev_join, 0);
}

// round 15
// speedup vs baseline: 1.3039x; 1.0162x over previous
#include <cuda_runtime.h>
#include <cstdint>

#define SQ   256
#define NH   16
#define HD   64
#define HIDW 1024
#define LOG2E 1.4426950408889634f

static __device__ float  g_Q[NH*SQ*HD];
static __device__ float  g_K[NH*SQ*HD + 2048];     // padded: prefetch overshoot
static __device__ float  g_V[NH*SQ*HD];
static __device__ float  g_S[NH*SQ*SQ];
static __device__ float  g_P[NH*SQ*SQ];
static __device__ float  g_Ctx[SQ*HIDW];
static __device__ float  g_Part[NH*SQ*HD];         // [row][d]

__device__ __forceinline__ float ex2f(float x){ float y; asm("ex2.approx.ftz.f32 %0, %1;" : "=f"(y) : "f"(x)); return y; }
__device__ __forceinline__ float rcpf(float x){ float y; asm("rcp.approx.ftz.f32 %0, %1;" : "=f"(y) : "f"(x)); return y; }
__device__ __forceinline__ void pfL1(const void* p){ asm volatile("prefetch.global.L1 [%0];" :: "l"(p)); }

// mask-based tf32 split: hi = x truncated to tf32 mantissa (exactly
// representable), lo = x - hi (exact FADD).  lo fed raw to MMA (HW truncates).
__device__ __forceinline__ void split2(float x, float& hi, float& lo){
    hi = __uint_as_float(__float_as_uint(x) & 0xFFFFE000u);
    lo = x - hi;
}

__device__ __forceinline__ void mma8(float* c, const uint32_t* a, const uint32_t* b){
    asm volatile("mma.sync.aligned.m16n8k8.row.col.f32.tf32.tf32.f32 "
        "{%0,%1,%2,%3}, {%4,%5,%6,%7}, {%8,%9}, {%0,%1,%2,%3};"
        : "+f"(c[0]), "+f"(c[1]), "+f"(c[2]), "+f"(c[3])
        : "r"(a[0]), "r"(a[1]), "r"(a[2]), "r"(a[3]), "r"(b[0]), "r"(b[1]));
}

// ---------------------------------------------------------------------------
// tf32-split GEMM, double-buffered smem mainloop.
// NT3=1: 3-term split — fp32-grade (QKV, scores: feed the amplifying path).
// NT3=0: 2-term, A raw — ~2^-12 (ctx, dense: linear path to `out`).
// MODE 0: fused = hidden @ Wqkv (+bias) -> scatter Q/K/V
// MODE 1: S[h]  = Q[h] @ K[h]^T   (B transposed at staging)
// MODE 2: Ctx   = P[h] @ V[h]
// MODE 3: out   = Ctx @ Wd (+bias+residual)
// ---------------------------------------------------------------------------
#define BSZ (32*72)

template<int MODE, int MT, int NT3>
__global__ void __launch_bounds__(256, 1) mma_gemm_k(const float* __restrict__ Aext,
                                                     const float* __restrict__ Bext,
                                                     const float* __restrict__ bias,
                                                     const float* __restrict__ resid,
                                                     float* __restrict__ outp)
{
    constexpr int KT  = (MODE==1) ? 64 : (MODE==2) ? 256 : 1024;
    constexpr int NK  = KT/32;
    constexpr int LDA = (MODE==1) ? 64 : (MODE==2) ? 256 : 1024;
    constexpr int LDB = (MODE==0) ? 3072 : (MODE==1) ? 64 : (MODE==2) ? 64 : 1024;
    constexpr int BM  = 64*MT;
    constexpr int AST = BM + 8;
    constexpr int ASZ = 32*AST;
    constexpr int NA  = NT3 ? 2 : 1;
    constexpr int SETSZ = NA*ASZ + 2*BSZ;

    extern __shared__ float sm[];

    const int tid = threadIdx.x, lane = tid & 31, wid = tid >> 5;
    const int wm = wid >> 1, wn = wid & 1;
    const int tig = lane & 3, gid = lane >> 2;
    const int n0 = blockIdx.x*64, m0 = blockIdx.y*BM, z = blockIdx.z;

    const float* Ag; const float* Bg;
    if constexpr (MODE==0)      { Ag = Aext;                  Bg = Bext; }
    else if constexpr (MODE==1) { Ag = g_Q + z*SQ*HD;         Bg = g_K + z*SQ*HD; }
    else if constexpr (MODE==2) { Ag = g_P + (size_t)z*SQ*SQ; Bg = g_V + z*SQ*HD; }
    else                        { Ag = g_Ctx;                 Bg = Bext; }

    const int kqw = tid & 3, mrw = (tid >> 2) & 7, aw = tid >> 5;
    float4 pa[2*MT]; float4 pb[2]; float pbt[8];

    auto loadA = [&](int kt){
#pragma unroll
        for (int mi = 0; mi < MT; mi++)
#pragma unroll
            for (int ki = 0; ki < 2; ki++) {
                int m = aw*8 + mrw + 64*mi, kq = kqw + 4*ki;
                pa[mi*2+ki] = *(const float4*)(Ag + (size_t)(m0+m)*LDA + kt*32 + kq*4);
            }
    };
    auto loadB = [&](int kt){
        if constexpr (MODE==1) {
            int d = tid & 31, jb = (tid >> 5) * 8;
#pragma unroll
            for (int r = 0; r < 8; r++)
                pbt[r] = Bg[(size_t)(n0 + jb + r)*LDB + kt*32 + d];
        } else {
#pragma unroll
            for (int r = 0; r < 2; r++) {
                int idx = tid + 256*r, kr = idx >> 4, nq = idx & 15;
                pb[r] = *(const float4*)(Bg + (size_t)(kt*32 + kr)*LDB + n0 + nq*4);
            }
        }
    };
    auto stage = [&](int buf){
        float* Ah = sm + buf*SETSZ;
        float* Al = Ah + ASZ;
        float* Bh = Ah + NA*ASZ;
        float* Bl = Bh + BSZ;
#pragma unroll
        for (int mi = 0; mi < MT; mi++)
#pragma unroll
            for (int ki = 0; ki < 2; ki++) {
                int m = aw*8 + mrw + 64*mi, kq = kqw + 4*ki;
                int mb = m ^ ((kq & 3) << 3);
                float4 v = pa[mi*2+ki];
                float vv[4] = {v.x, v.y, v.z, v.w};
#pragma unroll
                for (int e = 0; e < 4; e++) {
                    if constexpr (NT3) {
                        float hf, lf;
                        split2(vv[e], hf, lf);
                        Ah[(kq*4+e)*AST + mb] = hf;
                        Al[(kq*4+e)*AST + mb] = lf;
                    } else {
                        Ah[(kq*4+e)*AST + mb] = vv[e];
                    }
                }
            }
        if constexpr (MODE==1) {
            int d = tid & 31, jb = (tid >> 5) * 8;
            int C = ((d >> 2) & 3) << 3;
#pragma unroll
            for (int r = 0; r < 8; r++) {
                float hf, lf;
                split2(pbt[r], hf, lf);
                int off = d*72 + ((jb + r) ^ C);
                Bh[off] = hf; Bl[off] = lf;
            }
        } else {
#pragma unroll
            for (int r = 0; r < 2; r++) {
                int idx = tid + 256*r, kr = idx >> 4, nq = idx & 15;
                int off = kr*72 + ((nq*4) ^ (((kr >> 2) & 3) << 3));
                float4 v = pb[r];
                float4 h4, l4;
                split2(v.x, h4.x, l4.x);
                split2(v.y, h4.y, l4.y);
                split2(v.z, h4.z, l4.z);
                split2(v.w, h4.w, l4.w);
                *(float4*)(Bh + off) = h4;
                *(float4*)(Bl + off) = l4;
            }
        }
    };

    float acc[MT][4][4];
#pragma unroll
    for (int a = 0; a < MT; a++)
#pragma unroll
        for (int b = 0; b < 4; b++)
#pragma unroll
            for (int c = 0; c < 4; c++) acc[a][b][c] = 0.f;

    auto mmaOn = [&](int buf){
        const uint32_t* Ahu = (const uint32_t*)(sm + buf*SETSZ);
        const uint32_t* Alu = Ahu + ASZ;
        const uint32_t* Bhu = Ahu + NA*ASZ;
        const uint32_t* Blu = Bhu + BSZ;
#pragma unroll
        for (int ks = 0; ks < 4; ks++) {
            uint32_t ah[MT][4], al2[MT][4], bh[4][2], bl2[4][2];
            const int kA = ks*8 + tig;
            const int C0 = ((kA >> 2) & 3) << 3;
            const int C1 = (((kA + 4) >> 2) & 3) << 3;
#pragma unroll
            for (int mt = 0; mt < MT; mt++) {
                int m = wm*(16*MT) + mt*16 + gid;
                int mxa = m ^ C0, mya = m ^ C1;
                int i0 = kA*AST, i1 = (kA+4)*AST;
                ah[mt][0]  = Ahu[i0 + mxa];       ah[mt][1]  = Ahu[i0 + (mxa ^ 8)];
                ah[mt][2]  = Ahu[i1 + mya];       ah[mt][3]  = Ahu[i1 + (mya ^ 8)];
                if constexpr (NT3) {
                    al2[mt][0] = Alu[i0 + mxa];   al2[mt][1] = Alu[i0 + (mxa ^ 8)];
                    al2[mt][2] = Alu[i1 + mya];   al2[mt][3] = Alu[i1 + (mya ^ 8)];
                }
            }
#pragma unroll
            for (int nt = 0; nt < 4; nt++) {
                int n = wn*32 + nt*8 + gid;
                bh[nt][0]  = Bhu[kA*72 + (n ^ C0)];
                bh[nt][1]  = Bhu[(kA+4)*72 + (n ^ C1)];
                bl2[nt][0] = Blu[kA*72 + (n ^ C0)];
                bl2[nt][1] = Blu[(kA+4)*72 + (n ^ C1)];
            }
#pragma unroll
            for (int mt = 0; mt < MT; mt++)
#pragma unroll
                for (int nt = 0; nt < 4; nt++) {
                    mma8(acc[mt][nt], ah[mt],  bh[nt]);
                    mma8(acc[mt][nt], ah[mt],  bl2[nt]);
                    if constexpr (NT3)
                        mma8(acc[mt][nt], al2[mt], bh[nt]);
                }
        }
    };

    loadA(0); loadB(0);
    stage(0);
    __syncthreads();
    for (int kt = 0; kt < NK; kt++) {
        if (kt + 1 < NK) { loadA(kt+1); loadB(kt+1); }
        mmaOn(kt & 1);
        if (kt + 1 < NK) stage((kt+1) & 1);
        __syncthreads();
    }

#pragma unroll
    for (int mt = 0; mt < MT; mt++) {
        int m = m0 + wm*(16*MT) + mt*16 + gid;
#pragma unroll
        for (int nt = 0; nt < 4; nt++) {
            int n = n0 + wn*32 + nt*8 + tig*2;
            float c0 = acc[mt][nt][0], c1 = acc[mt][nt][1];
            float c2 = acc[mt][nt][2], c3 = acc[mt][nt][3];
            if constexpr (MODE==0) {
                float2 bb = *(const float2*)(bias + n);
                int hh = n / 192, rem = n - hh*192, wch = rem >> 6, d = rem & 63;
                float* base = (wch == 0) ? g_Q : (wch == 1) ? g_K : g_V;
                *(float2*)(base + (size_t)(hh*SQ + m)*HD + d)     = make_float2(c0 + bb.x, c1 + bb.y);
                *(float2*)(base + (size_t)(hh*SQ + m + 8)*HD + d) = make_float2(c2 + bb.x, c3 + bb.y);
            } else if constexpr (MODE==1) {
                *(float2*)(g_S + (size_t)(z*SQ + m)*SQ + n)     = make_float2(c0, c1);
                *(float2*)(g_S + (size_t)(z*SQ + m + 8)*SQ + n) = make_float2(c2, c3);
            } else if constexpr (MODE==2) {
                *(float2*)(g_Ctx + (size_t)m*HIDW + z*HD + n)       = make_float2(c0, c1);
                *(float2*)(g_Ctx + (size_t)(m + 8)*HIDW + z*HD + n) = make_float2(c2, c3);
            } else {
                float2 bb = *(const float2*)(bias + n);
                float2 r0 = *(const float2*)(resid + (size_t)m*HIDW + n);
                float2 r1 = *(const float2*)(resid + (size_t)(m + 8)*HIDW + n);
                *(float2*)(outp + (size_t)m*HIDW + n)       = make_float2(c0 + bb.x + r0.x, c1 + bb.y + r0.y);
                *(float2*)(outp + (size_t)(m + 8)*HIDW + n) = make_float2(c2 + bb.x + r1.x, c3 + bb.y + r1.y);
            }
        }
    }
}

// ---------------------------------------------------------------------------
// Slim warp-per-row softmax: writes ONLY g_P (ctx input).  The importance
// kernel computes its own per-row softmax internally.
// ---------------------------------------------------------------------------
__global__ void __launch_bounds__(256) softmax_p(const float* __restrict__ alibi,
                                                 const float* __restrict__ mask)
{
    const int w = threadIdx.x >> 5, ln = threadIdx.x & 31;
    const int row = blockIdx.x*8 + w;
    const int h = row >> 8, i = row & 255;
    const int j0 = ln*8;

    float4 s0 = *(const float4*)(g_S + (size_t)row*SQ + j0);
    float4 s1 = *(const float4*)(g_S + (size_t)row*SQ + j0 + 4);
    float4 a0 = *(const float4*)(alibi + h*SQ + j0);
    float4 a1 = *(const float4*)(alibi + h*SQ + j0 + 4);
    float4 k0 = *(const float4*)(mask + (size_t)i*SQ + j0);
    float4 k1 = *(const float4*)(mask + (size_t)i*SQ + j0 + 4);

    float sv[8] = {s0.x, s0.y, s0.z, s0.w, s1.x, s1.y, s1.z, s1.w};
    float al[8] = {a0.x, a0.y, a0.z, a0.w, a1.x, a1.y, a1.z, a1.w};
    float mk[8] = {k0.x, k0.y, k0.z, k0.w, k1.x, k1.y, k1.z, k1.w};

    float sc[8];
#pragma unroll
    for (int t = 0; t < 8; t++) sc[t] = fmaf(0.125f, sv[t], al[t]) + mk[t];

    float mx = sc[0];
#pragma unroll
    for (int t = 1; t < 8; t++) mx = fmaxf(mx, sc[t]);
#pragma unroll
    for (int o = 16; o; o >>= 1) mx = fmaxf(mx, __shfl_xor_sync(0xffffffffu, mx, o));

    float e[8], tot = 0.f;
#pragma unroll
    for (int t = 0; t < 8; t++) { e[t] = ex2f((sc[t] - mx) * LOG2E); tot += e[t]; }
#pragma unroll
    for (int o = 16; o; o >>= 1) tot += __shfl_xor_sync(0xffffffffu, tot, o);

    float iz = rcpf(tot);
    float p[8];
#pragma unroll
    for (int t = 0; t < 8; t++) p[t] = e[t] * iz;

    *(float4*)(g_P + (size_t)row*SQ + j0)     = make_float4(p[0], p[1], p[2], p[3]);
    *(float4*)(g_P + (size_t)row*SQ + j0 + 4) = make_float4(p[4], p[5], p[6], p[7]);
}

// ---------------------------------------------------------------------------
// qk_importance v6: block per (h, pair(i1,255-i1)).  Depends only on S/Q/K —
// computes the softmax of its two rows IN-BLOCK (S -> sc -> max/sum reduce ->
// p, A, P2), then runs the v5 pipelined loop on smem AP + register-pipelined K.
// All reductions fixed-order (deterministic).
// ---------------------------------------------------------------------------
__global__ void __launch_bounds__(256, 5) importance_k(const float* __restrict__ alibi,
                                                       const float* __restrict__ mask)
{
    __shared__ float  sm_red[6*512];
    __shared__ float2 sm_ap[2*256];
    __shared__ float  sm_w[8], sm_w2[8], sm_p2[8];
    const int tid = threadIdx.x;
    const int dp  = tid & 31;
    const int par = tid >> 5;
    const int h   = blockIdx.x >> 7;
    const int i1  = blockIdx.x & 127;
    const int i2  = 255 - i1;
    const int row1 = h*SQ + i1, row2 = h*SQ + i2;

    // K pipeline prologue (issued early; consumed after the softmax phase)
    const float2* kp = (const float2*)(g_K + (size_t)h*SQ*HD) + dp;
    int j = 2*par;
    float2 k0 = kp[(size_t)j*32], k1 = kp[(size_t)(j+1)*32];

    // ---- in-block softmax for rows (i1, i2): sm_ap = (A, p), sm_p2 ----
    {
        const int r    = tid >> 7;            // 0: row1 (warps 0-3), 1: row2
        const int jj   = (tid & 127) * 2;
        const int row  = r ? row2 : row1;
        const int irow = r ? i2 : i1;
        float2 s  = *(const float2*)(g_S + (size_t)row*SQ + jj);
        float2 av = *(const float2*)(alibi + h*SQ + jj);
        float2 mk = *(const float2*)(mask + (size_t)irow*SQ + jj);
        float sc0 = fmaf(0.125f, s.x, av.x) + mk.x;
        float sc1 = fmaf(0.125f, s.y, av.y) + mk.y;
        float m = fmaxf(sc0, sc1);
#pragma unroll
        for (int o = 16; o; o >>= 1) m = fmaxf(m, __shfl_xor_sync(0xffffffffu, m, o));
        if ((tid & 31) == 0) sm_w[par] = m;
        __syncthreads();
        const int rb = r*4;
        float bm = fmaxf(fmaxf(sm_w[rb], sm_w[rb+1]), fmaxf(sm_w[rb+2], sm_w[rb+3]));
        float e0 = ex2f((sc0 - bm)*LOG2E), e1v = ex2f((sc1 - bm)*LOG2E);
        float su = e0 + e1v;
#pragma unroll
        for (int o = 16; o; o >>= 1) su += __shfl_xor_sync(0xffffffffu, su, o);
        if ((tid & 31) == 0) sm_w2[par] = su;
        __syncthreads();
        float tot = (sm_w2[rb] + sm_w2[rb+1]) + (sm_w2[rb+2] + sm_w2[rb+3]);
        float iz = rcpf(tot);
        float p0 = e0*iz, p1 = e1v*iz;
        float a0 = (jj     <= irow) ? ex2f(s.x*(LOG2E/64.f)) : 0.f;
        float a1 = (jj + 1 <= irow) ? ex2f(s.y*(LOG2E/64.f)) : 0.f;
        sm_ap[r*256 + jj]     = make_float2(a0, p0);
        sm_ap[r*256 + jj + 1] = make_float2(a1, p1);
        float pq = fmaf(p0, p0, p1*p1);
#pragma unroll
        for (int o = 16; o; o >>= 1) pq += __shfl_xor_sync(0xffffffffu, pq, o);
        if ((tid & 31) == 0) sm_p2[par] = pq;
    }

    const float cc = -LOG2E/64.f;
    float2 q1 = *(const float2*)(g_Q + row1*HD + 2*dp);
    float2 q2 = *(const float2*)(g_Q + row2*HD + 2*dp);
    const float qe1x = q1.x*cc, qe1y = q1.y*cc, qe2x = q2.x*cc, qe2y = q2.y*cc;
    const float4* sap1 = (const float4*)sm_ap;
    const float4* sap2 = (const float4*)sm_ap + 128;

    float Z1x=0.f, Z1y=0.f, W1x=0.f, W1y=0.f, P1x=0.f, P1y=0.f;
    float Z2x=0.f, Z2y=0.f, W2x=0.f, W2y=0.f, P2x=0.f, P2y=0.f;

    const int e1 = (i1 + 16) & ~15;
    const int e2 = (i2 + 16) & ~15;
    __syncthreads();                          // AP smem ready

    for (; j < e1; j += 16) {
        float2 nk0 = kp[(size_t)(j+16)*32], nk1 = kp[(size_t)(j+17)*32];
        pfL1(&kp[(size_t)(j+32)*32]);
        float4 u = sap1[j>>1];
        float4 v = sap2[j>>1];

        float E0x = ex2f(qe1x*k0.x), E0y = ex2f(qe1y*k0.y);
        float E1x = ex2f(qe1x*k1.x), E1y = ex2f(qe1y*k1.y);
        float F0x = ex2f(qe2x*k0.x), F0y = ex2f(qe2y*k0.y);
        float F1x = ex2f(qe2x*k1.x), F1y = ex2f(qe2y*k1.y);
        float w;
        w = u.x*E0x; Z1x += w; W1x = fmaf(w,w,W1x); P1x = fmaf(w,u.y,P1x);
        w = u.x*E0y; Z1y += w; W1y = fmaf(w,w,W1y); P1y = fmaf(w,u.y,P1y);
        w = u.z*E1x; Z1x += w; W1x = fmaf(w,w,W1x); P1x = fmaf(w,u.w,P1x);
        w = u.z*E1y; Z1y += w; W1y = fmaf(w,w,W1y); P1y = fmaf(w,u.w,P1y);
        w = v.x*F0x; Z2x += w; W2x = fmaf(w,w,W2x); P2x = fmaf(w,v.y,P2x);
        w = v.x*F0y; Z2y += w; W2y = fmaf(w,w,W2y); P2y = fmaf(w,v.y,P2y);
        w = v.z*F1x; Z2x += w; W2x = fmaf(w,w,W2x); P2x = fmaf(w,v.w,P2x);
        w = v.z*F1y; Z2y += w; W2y = fmaf(w,w,W2y); P2y = fmaf(w,v.w,P2y);

        k0 = nk0; k1 = nk1;
    }
    for (; j < e2; j += 16) {
        float2 nk0 = kp[(size_t)(j+16)*32], nk1 = kp[(size_t)(j+17)*32];
        pfL1(&kp[(size_t)(j+32)*32]);
        float4 v = sap2[j>>1];

        float F0x = ex2f(qe2x*k0.x), F0y = ex2f(qe2y*k0.y);
        float F1x = ex2f(qe2x*k1.x), F1y = ex2f(qe2y*k1.y);
        float w;
        w = v.x*F0x; Z2x += w; W2x = fmaf(w,w,W2x); P2x = fmaf(w,v.y,P2x);
        w = v.x*F0y; Z2y += w; W2y = fmaf(w,w,W2y); P2y = fmaf(w,v.y,P2y);
        w = v.z*F1x; Z2x += w; W2x = fmaf(w,w,W2x); P2x = fmaf(w,v.w,P2x);
        w = v.z*F1y; Z2y += w; W2y = fmaf(w,w,W2y); P2y = fmaf(w,v.w,P2y);

        k0 = nk0; k1 = nk1;
    }

    float2* s2 = (float2*)sm_red;
    const int base = par*32 + dp;
    s2[0*256 + base] = make_float2(Z1x, Z1y);
    s2[1*256 + base] = make_float2(W1x, W1y);
    s2[2*256 + base] = make_float2(P1x, P1y);
    s2[3*256 + base] = make_float2(Z2x, Z2y);
    s2[4*256 + base] = make_float2(W2x, W2y);
    s2[5*256 + base] = make_float2(P2x, P2y);
    __syncthreads();
    if (tid < 128) {
        const int r = tid >> 6, d = tid & 63;
        const int qb = 3*r;
        float Z = 0.f, W = 0.f, P = 0.f;
#pragma unroll
        for (int pp = 0; pp < 8; pp++) {
            Z += sm_red[(qb+0)*512 + pp*64 + d];
            W += sm_red[(qb+1)*512 + pp*64 + d];
            P += sm_red[(qb+2)*512 + pp*64 + d];
        }
        const int row = r ? row2 : row1;
        float P2r = (sm_p2[r*4+0] + sm_p2[r*4+1]) + (sm_p2[r*4+2] + sm_p2[r*4+3]);
        float iz = rcpf(Z);
        g_Part[row*HD + d] = fmaf(W*iz, iz, -2.f*P*iz) + P2r;
    }
}

// Single-kernel deterministic reduction: block per head.
__global__ void __launch_bounds__(256) reduce_imp(float* __restrict__ imp)
{
    __shared__ float s[4][64];
    const int h = blockIdx.x, rr = threadIdx.x >> 6, d = threadIdx.x & 63;
    float s0 = 0.f;
#pragma unroll 8
    for (int r = 0; r < 64; ++r)
        s0 += g_Part[(h*SQ + rr*64 + r)*HD + d];
    s[rr][d] = s0;
    __syncthreads();
    if (threadIdx.x < 64)
        imp[h*64 + threadIdx.x] = (s[0][threadIdx.x] + s[1][threadIdx.x])
                                + (s[2][threadIdx.x] + s[3][threadIdx.x]);
}

// ---------------------------------------------------------------------------
extern "C" void kernel_launch(void* const* d_in, const int* in_sizes, int n_in,
                              void* d_out, int out_size)
{
    (void)in_sizes; (void)n_in; (void)out_size;
    const float* hidden   = (const float*)d_in[0];
    const float* residual = (const float*)d_in[1];
    const float* alibi    = (const float*)d_in[2];
    const float* amask    = (const float*)d_in[3];
    const float* Wqkv     = (const float*)d_in[4];
    const float* bqkv     = (const float*)d_in[5];
    const float* Wd       = (const float*)d_in[6];
    const float* bd       = (const float*)d_in[7];
    float* out = (float*)d_out;

    // persistent side stream + fork/join events (created once; capture-legal)
    static cudaStream_t s_imp = nullptr;
    static cudaEvent_t  ev_fork = nullptr, ev_join = nullptr;
    if (s_imp == nullptr) {
        cudaStreamCreateWithFlags(&s_imp, cudaStreamNonBlocking);
        cudaEventCreateWithFlags(&ev_fork, cudaEventDisableTiming);
        cudaEventCreateWithFlags(&ev_join, cudaEventDisableTiming);
    }

    constexpr int SMEM2  = 2*(2*32*136 + 2*BSZ)*4;  // MT=2, NT3=1: 106496
    constexpr int SMEM1S = 2*(1*32*72  + 2*BSZ)*4;  // MT=1, NT3=0: 55296

    cudaFuncSetAttribute(mma_gemm_k<0,2,1>, cudaFuncAttributeMaxDynamicSharedMemorySize, SMEM2);
    cudaFuncSetAttribute(mma_gemm_k<1,2,1>, cudaFuncAttributeMaxDynamicSharedMemorySize, SMEM2);
    cudaFuncSetAttribute(mma_gemm_k<2,1,0>, cudaFuncAttributeMaxDynamicSharedMemorySize, SMEM1S);
    cudaFuncSetAttribute(mma_gemm_k<3,1,0>, cudaFuncAttributeMaxDynamicSharedMemorySize, SMEM1S);

    // 1. QKV projection + Q/K/V scatter (3-term)
    mma_gemm_k<0,2,1><<<dim3(48,2,1), 256, SMEM2>>>(hidden, Wqkv, bqkv, nullptr, nullptr);
    // 2. scores S = Q K^T per head (3-term)
    mma_gemm_k<1,2,1><<<dim3(4,2,16), 256, SMEM2>>>(nullptr, nullptr, nullptr, nullptr, nullptr);

    // fork right after scores: importance no longer depends on softmax
    cudaEventRecord(ev_fork, 0);
    cudaStreamWaitEvent(s_imp, ev_fork, 0);

    // side: importance (in-block softmax) + deterministic reduce
    importance_k<<<2048, 256, 0, s_imp>>>(alibi, amask);
    reduce_imp<<<16, 256, 0, s_imp>>>(out + SQ*HIDW);

    // main: slim softmax (p only) -> ctx -> dense
    softmax_p<<<512, 256>>>(alibi, amask);
    mma_gemm_k<2,1,0><<<dim3(1,4,16), 256, SMEM1S>>>(nullptr, nullptr, nullptr, nullptr, nullptr);
    mma_gemm_k<3,1,0><<<dim3(16,4,1), 256, SMEM1S>>>(nullptr, Wd, bd, residual, out);

    // join
    cudaEventRecord(ev_join, s_imp);
    cudaStreamWaitEvent(0, ev_join, 0);
}